// round 7
// baseline (speedup 1.0000x reference)
#include <cuda_runtime.h>
#include <cuda_bf16.h>
#include <math.h>

#define H      1024
#define H4     256          // H/4
#define VOUT   32000
#define ML     128
#define ATT    129          // ML + 1
#define GRID   148
#define BLOCK  512
#define WPB    (BLOCK/32)   // 16 warps per block
#define NWARPS (GRID*WPB)   // 2368
#define MAXSLOT 14          // max rows per warp

// ---------------- device scratch (static, no allocation) ----------------
__device__ float g_h[2][H];
__device__ float g_enc_out[ATT * H];
__device__ float g_attn[ATT];
__device__ float g_ctx[H];
__device__ float g_comb[H];
__device__ float g_logits[VOUT];
__device__ unsigned long long g_ptop[GRID][4]; // per-CTA top-4 packed (bf16-based)
__device__ float g_psum[GRID];                 // per-CTA sumexp wrt its own max
__device__ int g_tok;
__device__ __nv_bfloat16 g_wbf[(size_t)VOUT * H];  // 64MB bf16 copy of out_W (L2-resident)

__device__ unsigned g_bar_count = 0;
__device__ unsigned g_bar_gen   = 0;

// ---------------- helpers ----------------
__device__ __forceinline__ float wredsum(float v) {
#pragma unroll
    for (int o = 16; o > 0; o >>= 1) v += __shfl_xor_sync(0xffffffffu, v, o);
    return v;
}
__device__ __forceinline__ float wredmax(float v) {
#pragma unroll
    for (int o = 16; o > 0; o >>= 1) v = fmaxf(v, __shfl_xor_sync(0xffffffffu, v, o));
    return v;
}
__device__ __forceinline__ unsigned long long wredmaxu64(unsigned long long v) {
#pragma unroll
    for (int o = 16; o > 0; o >>= 1) {
        unsigned long long q = __shfl_xor_sync(0xffffffffu, v, o);
        if (q > v) v = q;
    }
    return v;
}

__device__ __forceinline__ unsigned long long packf(float v, int idx) {
    unsigned u = __float_as_uint(v);
    u = (u & 0x80000000u) ? ~u : (u | 0x80000000u);   // totally ordered float bits
    return ((unsigned long long)u << 32) | (unsigned)(~(unsigned)idx); // tie -> lowest idx
}
__device__ __forceinline__ float unpack_max(unsigned long long p) {
    unsigned u = (unsigned)(p >> 32);
    unsigned b = (u & 0x80000000u) ? (u & 0x7fffffffu) : ~u;
    return __uint_as_float(b);
}
__device__ __forceinline__ int unpack_idx(unsigned long long p) {
    return (int)(~(unsigned)(p & 0xffffffffu));
}

__device__ __forceinline__ float dot4(float4 a, float4 b) {
    return a.x * b.x + a.y * b.y + a.z * b.z + a.w * b.w;
}

// 8-elem bf16 dot against two float4 halves
__device__ __forceinline__ float bfdot8(uint4 w, float4 a, float4 b) {
    float2 p0 = __bfloat1622float2(*(__nv_bfloat162*)&w.x);
    float2 p1 = __bfloat1622float2(*(__nv_bfloat162*)&w.y);
    float2 p2 = __bfloat1622float2(*(__nv_bfloat162*)&w.z);
    float2 p3 = __bfloat1622float2(*(__nv_bfloat162*)&w.w);
    return p0.x*a.x + p0.y*a.y + p1.x*a.z + p1.y*a.w
         + p2.x*b.x + p2.y*b.y + p3.x*b.z + p3.y*b.w;
}

// insert p into descending top-4 (c0>=c1>=c2>=c3)
__device__ __forceinline__ void top4_ins(unsigned long long& c0, unsigned long long& c1,
                                         unsigned long long& c2, unsigned long long& c3,
                                         unsigned long long p) {
    if (p > c0)      { c3 = c2; c2 = c1; c1 = c0; c0 = p; }
    else if (p > c1) { c3 = c2; c2 = c1; c1 = p; }
    else if (p > c2) { c3 = c2; c2 = p; }
    else if (p > c3) { c3 = p; }
}

// ---------------- grid-wide barrier (CG grid.sync pattern) ----------------
__device__ __forceinline__ unsigned ld_acq(unsigned* p) {
    unsigned v;
    asm volatile("ld.acquire.gpu.u32 %0, [%1];" : "=r"(v) : "l"(p) : "memory");
    return v;
}
__device__ __forceinline__ void st_rel(unsigned* p, unsigned v) {
    asm volatile("st.release.gpu.u32 [%0], %1;" :: "l"(p), "r"(v) : "memory");
}

__device__ __forceinline__ void gsync() {
    __syncthreads();
    if (threadIdx.x == 0) {
        unsigned gen = ld_acq(&g_bar_gen);
        __threadfence();
        if (atomicAdd(&g_bar_count, 1) == GRID - 1) {
            g_bar_count = 0;
            st_rel(&g_bar_gen, gen + 1);
        } else {
            while (ld_acq(&g_bar_gen) == gen) { }
        }
    }
    __syncthreads();
}

// ---------------- shared-memory layout ----------------
struct Smem {
    float e[ATT];                 // attention softmax weights
    float part[WPB][33];          // ctx partial sums (padded)
    float slot[WPB * MAXSLOT];    // raw logits per warp slot
    float red[BLOCK];             // tree-reduction scratch
    unsigned long long wtop[WPB][4];
    unsigned long long top4[4];
    unsigned long long cand[4];
    float bf[4];                  // scalar broadcasts
    unsigned long long bu;
};

// ---------------- phases ----------------

// GRU step: warp w<7 handles row = w*GRID + cta, all 6 dots.
__device__ __forceinline__ void gru_phase(
    const float* __restrict__ Wih, const float* __restrict__ Whh,
    const float* __restrict__ bih, const float* __restrict__ bhh,
    const float* __restrict__ x, const float* __restrict__ h,
    float* __restrict__ ho, float* __restrict__ enc_row)
{
    int wib = threadIdx.x >> 5;
    int lane = threadIdx.x & 31;
    if (wib >= 7) return;
    int row = wib * GRID + (int)blockIdx.x;
    if (row >= H) return;

    const float4* x4 = (const float4*)x;
    const float4* h4 = (const float4*)h;
    const float4* Wir = (const float4*)(Wih + (size_t)row * H);
    const float4* Wiz = (const float4*)(Wih + (size_t)(row + H) * H);
    const float4* Win = (const float4*)(Wih + (size_t)(row + 2 * H) * H);
    const float4* Whr = (const float4*)(Whh + (size_t)row * H);
    const float4* Whz = (const float4*)(Whh + (size_t)(row + H) * H);
    const float4* Whn = (const float4*)(Whh + (size_t)(row + 2 * H) * H);

    float ir = 0.f, iz = 0.f, inn = 0.f, hr = 0.f, hz = 0.f, hn = 0.f;
#pragma unroll 4
    for (int k = lane; k < H4; k += 32) {
        float4 xv = x4[k], hv = h4[k];
        ir  += dot4(Wir[k], xv);
        iz  += dot4(Wiz[k], xv);
        inn += dot4(Win[k], xv);
        hr  += dot4(Whr[k], hv);
        hz  += dot4(Whz[k], hv);
        hn  += dot4(Whn[k], hv);
    }
    ir = wredsum(ir);  iz = wredsum(iz);  inn = wredsum(inn);
    hr = wredsum(hr);  hz = wredsum(hz);  hn  = wredsum(hn);

    if (lane == 0) {
        ir  += bih[row];          hr += bhh[row];
        iz  += bih[row + H];      hz += bhh[row + H];
        inn += bih[row + 2 * H];  hn += bhh[row + 2 * H];
        float r = 1.f / (1.f + expf(-(ir + hr)));
        float z = 1.f / (1.f + expf(-(iz + hz)));
        float n = tanhf(inn + r * hn);
        float hnew = (1.f - z) * n + z * h[row];
        ho[row] = hnew;
        if (enc_row) enc_row[row] = hnew;
    }
}

// attention softmax + context. CTAs 0..31 each produce 32 ctx elements.
__device__ __forceinline__ void ctx_phase(Smem* sm)
{
    if ((int)blockIdx.x >= 32) return;
    int wib = threadIdx.x >> 5, lane = threadIdx.x & 31;

    if (wib == 0) {
        float v[5];
        float mx = -INFINITY;
#pragma unroll
        for (int k = 0; k < 5; k++) {
            int idx = lane + 32 * k;
            v[k] = (idx < ATT) ? g_attn[idx] : -INFINITY;
            mx = fmaxf(mx, v[k]);
        }
        mx = wredmax(mx);
        float s = 0.f;
#pragma unroll
        for (int k = 0; k < 5; k++) {
            int idx = lane + 32 * k;
            if (idx < ATT) {
                float e = expf(v[k] - mx);
                sm->e[idx] = e;
                s += e;
            }
        }
        s = wredsum(s);
        if (lane == 0) sm->bf[0] = 1.f / s;
    }
    __syncthreads();

    int j = (int)blockIdx.x * 32 + lane;
    float acc = 0.f;
    for (int t = wib; t < ATT; t += WPB)
        acc += sm->e[t] * g_enc_out[t * H + j];
    sm->part[wib][lane] = acc;
    __syncthreads();
    if (wib == 0) {
        float a = 0.f;
#pragma unroll
        for (int w = 0; w < WPB; w++) a += sm->part[w][lane];
        g_ctx[j] = a * sm->bf[0];
    }
}

// comb = relu(comb_W @ [emb; ctx] + b): one warp per row
__device__ __forceinline__ void comb_phase(
    const float* __restrict__ comb_W, const float* __restrict__ comb_b,
    const float* __restrict__ dec_emb)
{
    int wib = threadIdx.x >> 5;
    int lane = threadIdx.x & 31;
    if (wib >= 7) return;
    int row = wib * GRID + (int)blockIdx.x;
    if (row >= H) return;
    int tok = g_tok;
    const float4* W  = (const float4*)(comb_W + (size_t)row * 2 * H);
    const float4* e4 = (const float4*)(dec_emb + (size_t)tok * H);
    const float4* c4 = (const float4*)g_ctx;
    float a = 0.f;
#pragma unroll 4
    for (int k = lane; k < H4; k += 32) a += dot4(W[k], e4[k]);
#pragma unroll 4
    for (int k = lane; k < H4; k += 32) a += dot4(W[k + H4], c4[k]);
    a = wredsum(a);
    if (lane == 0) {
        a += comb_b[row];
        g_comb[row] = fmaxf(a, 0.f);
    }
}

// logits GEMV on bf16 weights (L2-resident, default caching): 4 rows per
// warp-iteration, branch-free epilogue, per-warp top-4 -> per-CTA partials.
__device__ __forceinline__ void logits_phase(
    const float* __restrict__ out_b, const float* __restrict__ h, Smem* sm)
{
    int tid = threadIdx.x, lane = tid & 31, wib = tid >> 5;
    int gw = (int)blockIdx.x * WPB + wib;

    if (tid < WPB * MAXSLOT) sm->slot[tid] = -INFINITY;
    __syncthreads();

    // h cached: hv[2i],hv[2i+1] cover elements (lane+32i)*8 .. +7
    const float4* h4 = (const float4*)h;
    float4 hv[8];
#pragma unroll
    for (int i = 0; i < 4; i++) {
        hv[2*i]   = h4[(lane + 32*i) * 2];
        hv[2*i+1] = h4[(lane + 32*i) * 2 + 1];
    }

    // n = 0..12 are always in-bounds (gw + 12*NWARPS <= 2367+28416 < 32000)
#pragma unroll 1
    for (int it = 0; it < 3; it++) {
        int r0 = gw + (4 * it)     * NWARPS;
        int r1 = gw + (4 * it + 1) * NWARPS;
        int r2 = gw + (4 * it + 2) * NWARPS;
        int r3 = gw + (4 * it + 3) * NWARPS;
        const uint4* W0 = (const uint4*)(g_wbf + (size_t)r0 * H);
        const uint4* W1 = (const uint4*)(g_wbf + (size_t)r1 * H);
        const uint4* W2 = (const uint4*)(g_wbf + (size_t)r2 * H);
        const uint4* W3 = (const uint4*)(g_wbf + (size_t)r3 * H);
        float a0 = 0.f, a1 = 0.f, a2 = 0.f, a3 = 0.f;
#pragma unroll
        for (int i = 0; i < 4; i++) {
            uint4 w0 = __ldg(&W0[lane + 32 * i]);
            uint4 w1 = __ldg(&W1[lane + 32 * i]);
            uint4 w2 = __ldg(&W2[lane + 32 * i]);
            uint4 w3 = __ldg(&W3[lane + 32 * i]);
            a0 += bfdot8(w0, hv[2*i], hv[2*i+1]);
            a1 += bfdot8(w1, hv[2*i], hv[2*i+1]);
            a2 += bfdot8(w2, hv[2*i], hv[2*i+1]);
            a3 += bfdot8(w3, hv[2*i], hv[2*i+1]);
        }
        a0 = wredsum(a0);
        a1 = wredsum(a1);
        a2 = wredsum(a2);
        a3 = wredsum(a3);
        if (lane == 0) {
            a0 += out_b[r0];  g_logits[r0] = a0;  sm->slot[wib * MAXSLOT + 4*it]     = a0;
            a1 += out_b[r1];  g_logits[r1] = a1;  sm->slot[wib * MAXSLOT + 4*it + 1] = a1;
            a2 += out_b[r2];  g_logits[r2] = a2;  sm->slot[wib * MAXSLOT + 4*it + 2] = a2;
            a3 += out_b[r3];  g_logits[r3] = a3;  sm->slot[wib * MAXSLOT + 4*it + 3] = a3;
        }
    }
    // tail: n = 12 (always valid) and n = 13 (conditional)
    {
        int r0 = gw + 12 * NWARPS;
        int r1 = gw + 13 * NWARPS;
        bool ok1 = (r1 < VOUT);
        const uint4* W0 = (const uint4*)(g_wbf + (size_t)r0 * H);
        const uint4* W1 = (const uint4*)(g_wbf + (size_t)(ok1 ? r1 : r0) * H);
        float a0 = 0.f, a1 = 0.f;
#pragma unroll
        for (int i = 0; i < 4; i++) {
            uint4 w0 = __ldg(&W0[lane + 32 * i]);
            uint4 w1 = __ldg(&W1[lane + 32 * i]);
            a0 += bfdot8(w0, hv[2*i], hv[2*i+1]);
            a1 += bfdot8(w1, hv[2*i], hv[2*i+1]);
        }
        a0 = wredsum(a0);
        a1 = wredsum(a1);
        if (lane == 0) {
            a0 += out_b[r0];  g_logits[r0] = a0;  sm->slot[wib * MAXSLOT + 12] = a0;
            if (ok1) {
                a1 += out_b[r1];  g_logits[r1] = a1;  sm->slot[wib * MAXSLOT + 13] = a1;
            }
        }
    }

    // per-warp top-4 scan (lane0, off the hot loop)
    if (lane == 0) {
        unsigned long long c0 = 0, c1 = 0, c2 = 0, c3 = 0;
#pragma unroll
        for (int n = 0; n < MAXSLOT; n++) {
            int row = gw + n * NWARPS;
            if (row < VOUT) {
                unsigned long long p = packf(sm->slot[wib * MAXSLOT + n], row);
                top4_ins(c0, c1, c2, c3, p);
            }
        }
        sm->wtop[wib][0] = c0; sm->wtop[wib][1] = c1;
        sm->wtop[wib][2] = c2; sm->wtop[wib][3] = c3;
    }
    __syncthreads();

    // warp0: pop-merge 16 warp lists -> CTA top-4
    if (wib == 0) {
        unsigned long long a0 = 0, a1 = 0, a2 = 0, a3 = 0;
        if (lane < WPB) {
            a0 = sm->wtop[lane][0]; a1 = sm->wtop[lane][1];
            a2 = sm->wtop[lane][2]; a3 = sm->wtop[lane][3];
        }
        int pos = 0;
        unsigned long long t[4];
#pragma unroll
        for (int k = 0; k < 4; k++) {
            unsigned long long head = (pos == 0) ? a0 : (pos == 1) ? a1 :
                                      (pos == 2) ? a2 : (pos == 3) ? a3 : 0ull;
            unsigned long long m = wredmaxu64(head);
            t[k] = m;
            if (head == m && pos < 4) pos++;
        }
        if (lane == 0) {
#pragma unroll
            for (int k = 0; k < 4; k++) g_ptop[blockIdx.x][k] = t[k];
            sm->bu = t[0];
        }
    }
    __syncthreads();

    // CTA sumexp wrt CTA max
    float m = unpack_max(sm->bu);
    float e = (tid < WPB * MAXSLOT) ? expf(sm->slot[tid] - m) : 0.f;
    sm->red[tid] = e; __syncthreads();
#pragma unroll
    for (int s = BLOCK / 2; s > 0; s >>= 1) {
        if (tid < s) sm->red[tid] += sm->red[tid + s];
        __syncthreads();
    }
    if (tid == 0) g_psum[blockIdx.x] = sm->red[0];
}

// global top-4 merge + lse; fp32 recheck of top-4 for exact argmax;
// write logp row; fuse next-step attention-logit prep
__device__ __forceinline__ void out_phase(
    float* __restrict__ out, int step,
    const float* __restrict__ out_W, const float* __restrict__ out_b,
    const float* __restrict__ attn_W, const float* __restrict__ attn_b,
    const float* __restrict__ dec_emb, const float* __restrict__ h, Smem* sm)
{
    int tid = threadIdx.x, lane = tid & 31, wib = tid >> 5;

    if (wib == 0) {
        // per-lane top-4 over its CTAs
        unsigned long long c0 = 0, c1 = 0, c2 = 0, c3 = 0;
        for (int cc = lane; cc < GRID; cc += 32) {
#pragma unroll
            for (int k = 0; k < 4; k++)
                top4_ins(c0, c1, c2, c3, g_ptop[cc][k]);
        }
        // pop-merge across lanes -> global top-4
        int pos = 0;
        unsigned long long t[4];
#pragma unroll
        for (int k = 0; k < 4; k++) {
            unsigned long long head = (pos == 0) ? c0 : (pos == 1) ? c1 :
                                      (pos == 2) ? c2 : (pos == 3) ? c3 : 0ull;
            unsigned long long mm = wredmaxu64(head);
            t[k] = mm;
            if (head == mm && pos < 4) pos++;
        }
        float M = unpack_max(t[0]);
        float S = 0.f;
        for (int cc = lane; cc < GRID; cc += 32)
            S += g_psum[cc] * expf(unpack_max(g_ptop[cc][0]) - M);
        S = wredsum(S);
        if (lane == 0) {
#pragma unroll
            for (int k = 0; k < 4; k++) sm->top4[k] = t[k];
            sm->bf[0] = M + logf(S);
        }
    }
    __syncthreads();
    float lse = sm->bf[0];

    // write logp row (bf16-based logits, fp32 lse)
    int g = (int)blockIdx.x * BLOCK + tid;
    if (g < VOUT) out[(size_t)step * VOUT + g] = g_logits[g] - lse;

    // fp32 recheck of the 4 candidates (warps 0..3, one row each)
    if (wib < 4) {
        int rk = unpack_idx(sm->top4[wib]);
        const float4* W = (const float4*)(out_W + (size_t)rk * H);
        const float4* h4 = (const float4*)h;
        float a = 0.f;
#pragma unroll 4
        for (int k = lane; k < H4; k += 32) a += dot4(W[k], h4[k]);
        a = wredsum(a);
        if (lane == 0) sm->cand[wib] = packf(a + out_b[rk], rk);
    }
    __syncthreads();
    unsigned long long w = sm->cand[0];
#pragma unroll
    for (int k = 1; k < 4; k++) if (sm->cand[k] > w) w = sm->cand[k];
    int tok = unpack_idx(w);

    // next-step attention logits: two-warp split per CTA row
    if ((int)blockIdx.x < ATT) {
        int r = (int)blockIdx.x;
        if (wib == 0) {        // emb half
            const float4* W  = (const float4*)(attn_W + (size_t)r * 2 * H);
            const float4* e4 = (const float4*)(dec_emb + (size_t)tok * H);
            float a = 0.f;
#pragma unroll 4
            for (int k = lane; k < H4; k += 32) a += dot4(W[k], e4[k]);
            a = wredsum(a);
            if (lane == 0) sm->bf[1] = a;
        } else if (wib == 8) { // h half
            const float4* W  = (const float4*)(attn_W + (size_t)r * 2 * H + H);
            const float4* h4 = (const float4*)h;
            float a = 0.f;
#pragma unroll 4
            for (int k = lane; k < H4; k += 32) a += dot4(W[k], h4[k]);
            a = wredsum(a);
            if (lane == 0) sm->bf[2] = a;
        }
        __syncthreads();
        if (tid == 0) g_attn[r] = sm->bf[1] + sm->bf[2] + attn_b[r];
    }
    if (blockIdx.x == 0 && tid == 0) g_tok = tok;
}

// ---------------- the single persistent kernel ----------------
__global__ void __launch_bounds__(BLOCK, 1) k_all(
    const int* __restrict__ tokens,
    const float* __restrict__ enc_emb,
    const float* __restrict__ enc_Wih, const float* __restrict__ enc_Whh,
    const float* __restrict__ enc_bih, const float* __restrict__ enc_bhh,
    const float* __restrict__ dec_emb,
    const float* __restrict__ attn_W, const float* __restrict__ attn_b,
    const float* __restrict__ comb_W, const float* __restrict__ comb_b,
    const float* __restrict__ dec_Wih, const float* __restrict__ dec_Whh,
    const float* __restrict__ dec_bih, const float* __restrict__ dec_bhh,
    const float* __restrict__ out_W, const float* __restrict__ out_b,
    float* __restrict__ out)
{
    __shared__ Smem sm;
    int tid = threadIdx.x;

    // one-time: convert out_W to bf16 (grid-stride, vectorized).
    // Read fp32 evict-first (streamed once); write bf16 with default policy
    // so the 64MB bf16 array lands (and stays) in L2.
    {
        const float4* w4 = (const float4*)out_W;
        uint2* dst = (uint2*)g_wbf;
        const int n4 = VOUT * (H / 4);
        for (int i = (int)blockIdx.x * BLOCK + tid; i < n4; i += GRID * BLOCK) {
            float4 v = __ldcs(&w4[i]);
            __nv_bfloat162 lo = __floats2bfloat162_rn(v.x, v.y);
            __nv_bfloat162 hi = __floats2bfloat162_rn(v.z, v.w);
            uint2 o;
            o.x = *(unsigned*)&lo;
            o.y = *(unsigned*)&hi;
            dst[i] = o;
        }
    }

    // init: h0 = 0, padding row of enc_out = 0
    {
        int g = (int)blockIdx.x * BLOCK + tid;
        if (g < H) { g_h[0][g] = 0.f; g_enc_out[ML * H + g] = 0.f; }
    }
    gsync();

    // ---- encoder ----
    for (int t = 0; t < ML; t++) {
        const float* x = enc_emb + (size_t)tokens[t] * H;
        gru_phase(enc_Wih, enc_Whh, enc_bih, enc_bhh, x,
                  g_h[t & 1], g_h[(t & 1) ^ 1], g_enc_out + (size_t)t * H);
        gsync();
    }
    // final encoder hidden in g_h[0]

    // ---- decoder prep (tok = SOS = 0): attention logits (two-warp split) ----
    if ((int)blockIdx.x < ATT) {
        int r = (int)blockIdx.x;
        int wib = tid >> 5, lane = tid & 31;
        if (wib == 0) {
            const float4* W  = (const float4*)(attn_W + (size_t)r * 2 * H);
            const float4* e4 = (const float4*)dec_emb;  // row 0 (SOS)
            float a = 0.f;
#pragma unroll 4
            for (int k = lane; k < H4; k += 32) a += dot4(W[k], e4[k]);
            a = wredsum(a);
            if (lane == 0) sm.bf[1] = a;
        } else if (wib == 8) {
            const float4* W  = (const float4*)(attn_W + (size_t)r * 2 * H + H);
            const float4* h4 = (const float4*)g_h[0];
            float a = 0.f;
#pragma unroll 4
            for (int k = lane; k < H4; k += 32) a += dot4(W[k], h4[k]);
            a = wredsum(a);
            if (lane == 0) sm.bf[2] = a;
        }
        __syncthreads();
        if (tid == 0) g_attn[r] = sm.bf[1] + sm.bf[2] + attn_b[r];
    }
    if (blockIdx.x == 0 && tid == 0) g_tok = 0;
    gsync();

    // ---- decoder ----
    for (int s = 0; s < ML; s++) {
        const float* hc = g_h[s & 1];
        float* hn = g_h[(s & 1) ^ 1];

        ctx_phase(&sm);                                        gsync();
        comb_phase(comb_W, comb_b, dec_emb);                   gsync();
        gru_phase(dec_Wih, dec_Whh, dec_bih, dec_bhh,
                  g_comb, hc, hn, nullptr);                    gsync();
        logits_phase(out_b, hn, &sm);                          gsync();
        out_phase(out, s, out_W, out_b, attn_W, attn_b,
                  dec_emb, hn, &sm);                           gsync();
    }
}

// ---------------- host launcher ----------------
extern "C" void kernel_launch(void* const* d_in, const int* in_sizes, int n_in,
                              void* d_out, int out_size)
{
    const int*   tokens  = (const int*)  d_in[0];
    // d_in[1] = max_length (compile-time ML=128)
    const float* enc_emb = (const float*)d_in[2];
    const float* enc_Wih = (const float*)d_in[3];
    const float* enc_Whh = (const float*)d_in[4];
    const float* enc_bih = (const float*)d_in[5];
    const float* enc_bhh = (const float*)d_in[6];
    const float* dec_emb = (const float*)d_in[7];
    const float* attn_W  = (const float*)d_in[8];
    const float* attn_b  = (const float*)d_in[9];
    const float* comb_W  = (const float*)d_in[10];
    const float* comb_b  = (const float*)d_in[11];
    const float* dec_Wih = (const float*)d_in[12];
    const float* dec_Whh = (const float*)d_in[13];
    const float* dec_bih = (const float*)d_in[14];
    const float* dec_bhh = (const float*)d_in[15];
    const float* out_W   = (const float*)d_in[16];
    const float* out_b   = (const float*)d_in[17];
    float* out = (float*)d_out;

    k_all<<<GRID, BLOCK>>>(tokens, enc_emb, enc_Wih, enc_Whh, enc_bih, enc_bhh,
                           dec_emb, attn_W, attn_b, comb_W, comb_b,
                           dec_Wih, dec_Whh, dec_bih, dec_bhh,
                           out_W, out_b, out);
}

// round 8
// speedup vs baseline: 1.1337x; 1.1337x over previous
#include <cuda_runtime.h>
#include <cuda_bf16.h>
#include <math.h>

#define H      1024
#define H4     256          // H/4
#define VOUT   32000
#define ML     128
#define ATT    129          // ML + 1
#define GRID   148
#define BLOCK  512
#define WPB    (BLOCK/32)   // 16 warps per block
#define NWARPS (GRID*WPB)   // 2368
#define MAXSLOT 14          // max rows per warp
// slots 0..5 (first 14208 rows, 29MB) stay L2-resident via __ldg;
// slots 6..13 (36.4MB) stream from DRAM via __ldcs.

// ---------------- device scratch (static, no allocation) ----------------
__device__ float g_h[2][H];
__device__ float g_enc_out[ATT * H];
__device__ float g_attn[ATT];
__device__ float g_ctx[H];
__device__ float g_comb[H];
__device__ float g_logits[VOUT];
__device__ unsigned long long g_ptop[GRID][4]; // per-CTA top-4 packed (bf16-based)
__device__ float g_psum[GRID];                 // per-CTA sumexp wrt its own max
__device__ int g_tok;
__device__ __nv_bfloat16 g_wbf[(size_t)VOUT * H];  // 64MB bf16 copy of out_W

__device__ unsigned g_bar_count = 0;
__device__ unsigned g_bar_gen   = 0;

// ---------------- helpers ----------------
__device__ __forceinline__ float wredsum(float v) {
#pragma unroll
    for (int o = 16; o > 0; o >>= 1) v += __shfl_xor_sync(0xffffffffu, v, o);
    return v;
}
__device__ __forceinline__ float wredmax(float v) {
#pragma unroll
    for (int o = 16; o > 0; o >>= 1) v = fmaxf(v, __shfl_xor_sync(0xffffffffu, v, o));
    return v;
}
__device__ __forceinline__ unsigned long long wredmaxu64(unsigned long long v) {
#pragma unroll
    for (int o = 16; o > 0; o >>= 1) {
        unsigned long long q = __shfl_xor_sync(0xffffffffu, v, o);
        if (q > v) v = q;
    }
    return v;
}

__device__ __forceinline__ unsigned long long packf(float v, int idx) {
    unsigned u = __float_as_uint(v);
    u = (u & 0x80000000u) ? ~u : (u | 0x80000000u);   // totally ordered float bits
    return ((unsigned long long)u << 32) | (unsigned)(~(unsigned)idx); // tie -> lowest idx
}
__device__ __forceinline__ float unpack_max(unsigned long long p) {
    unsigned u = (unsigned)(p >> 32);
    unsigned b = (u & 0x80000000u) ? (u & 0x7fffffffu) : ~u;
    return __uint_as_float(b);
}
__device__ __forceinline__ int unpack_idx(unsigned long long p) {
    return (int)(~(unsigned)(p & 0xffffffffu));
}

__device__ __forceinline__ float dot4(float4 a, float4 b) {
    return a.x * b.x + a.y * b.y + a.z * b.z + a.w * b.w;
}

// 8-elem bf16 dot against two float4 halves
__device__ __forceinline__ float bfdot8(uint4 w, float4 a, float4 b) {
    float2 p0 = __bfloat1622float2(*(__nv_bfloat162*)&w.x);
    float2 p1 = __bfloat1622float2(*(__nv_bfloat162*)&w.y);
    float2 p2 = __bfloat1622float2(*(__nv_bfloat162*)&w.z);
    float2 p3 = __bfloat1622float2(*(__nv_bfloat162*)&w.w);
    return p0.x*a.x + p0.y*a.y + p1.x*a.z + p1.y*a.w
         + p2.x*b.x + p2.y*b.y + p3.x*b.z + p3.y*b.w;
}

// insert p into descending top-4 (c0>=c1>=c2>=c3)
__device__ __forceinline__ void top4_ins(unsigned long long& c0, unsigned long long& c1,
                                         unsigned long long& c2, unsigned long long& c3,
                                         unsigned long long p) {
    if (p > c0)      { c3 = c2; c2 = c1; c1 = c0; c0 = p; }
    else if (p > c1) { c3 = c2; c2 = c1; c1 = p; }
    else if (p > c2) { c3 = c2; c2 = p; }
    else if (p > c3) { c3 = p; }
}

// ---------------- grid-wide barrier (CG grid.sync pattern) ----------------
__device__ __forceinline__ unsigned ld_acq(unsigned* p) {
    unsigned v;
    asm volatile("ld.acquire.gpu.u32 %0, [%1];" : "=r"(v) : "l"(p) : "memory");
    return v;
}
__device__ __forceinline__ void st_rel(unsigned* p, unsigned v) {
    asm volatile("st.release.gpu.u32 [%0], %1;" :: "l"(p), "r"(v) : "memory");
}

__device__ __forceinline__ void gsync() {
    __syncthreads();
    if (threadIdx.x == 0) {
        unsigned gen = ld_acq(&g_bar_gen);
        __threadfence();
        if (atomicAdd(&g_bar_count, 1) == GRID - 1) {
            g_bar_count = 0;
            st_rel(&g_bar_gen, gen + 1);
        } else {
            while (ld_acq(&g_bar_gen) == gen) { }
        }
    }
    __syncthreads();
}

// ---------------- shared-memory layout ----------------
struct Smem {
    float e[ATT];                 // attention softmax weights
    float part[WPB][33];          // ctx partial sums (padded)
    float slot[WPB * MAXSLOT];    // raw logits per warp slot
    float red[BLOCK];             // tree-reduction scratch
    unsigned long long wtop[WPB][4];
    unsigned long long top4[4];
    unsigned long long cand[4];
    float bf[4];                  // scalar broadcasts
    unsigned long long bu;
};

// ---------------- phases ----------------

// GRU step: warp w<7 handles row = w*GRID + cta, all 6 dots.
__device__ __forceinline__ void gru_phase(
    const float* __restrict__ Wih, const float* __restrict__ Whh,
    const float* __restrict__ bih, const float* __restrict__ bhh,
    const float* __restrict__ x, const float* __restrict__ h,
    float* __restrict__ ho, float* __restrict__ enc_row)
{
    int wib = threadIdx.x >> 5;
    int lane = threadIdx.x & 31;
    if (wib >= 7) return;
    int row = wib * GRID + (int)blockIdx.x;
    if (row >= H) return;

    const float4* x4 = (const float4*)x;
    const float4* h4 = (const float4*)h;
    const float4* Wir = (const float4*)(Wih + (size_t)row * H);
    const float4* Wiz = (const float4*)(Wih + (size_t)(row + H) * H);
    const float4* Win = (const float4*)(Wih + (size_t)(row + 2 * H) * H);
    const float4* Whr = (const float4*)(Whh + (size_t)row * H);
    const float4* Whz = (const float4*)(Whh + (size_t)(row + H) * H);
    const float4* Whn = (const float4*)(Whh + (size_t)(row + 2 * H) * H);

    float ir = 0.f, iz = 0.f, inn = 0.f, hr = 0.f, hz = 0.f, hn = 0.f;
#pragma unroll 4
    for (int k = lane; k < H4; k += 32) {
        float4 xv = x4[k], hv = h4[k];
        ir  += dot4(Wir[k], xv);
        iz  += dot4(Wiz[k], xv);
        inn += dot4(Win[k], xv);
        hr  += dot4(Whr[k], hv);
        hz  += dot4(Whz[k], hv);
        hn  += dot4(Whn[k], hv);
    }
    ir = wredsum(ir);  iz = wredsum(iz);  inn = wredsum(inn);
    hr = wredsum(hr);  hz = wredsum(hz);  hn  = wredsum(hn);

    if (lane == 0) {
        ir  += bih[row];          hr += bhh[row];
        iz  += bih[row + H];      hz += bhh[row + H];
        inn += bih[row + 2 * H];  hn += bhh[row + 2 * H];
        float r = 1.f / (1.f + expf(-(ir + hr)));
        float z = 1.f / (1.f + expf(-(iz + hz)));
        float n = tanhf(inn + r * hn);
        float hnew = (1.f - z) * n + z * h[row];
        ho[row] = hnew;
        if (enc_row) enc_row[row] = hnew;
    }
}

// attention softmax + context. CTAs 0..31 each produce 32 ctx elements.
__device__ __forceinline__ void ctx_phase(Smem* sm)
{
    if ((int)blockIdx.x >= 32) return;
    int wib = threadIdx.x >> 5, lane = threadIdx.x & 31;

    if (wib == 0) {
        float v[5];
        float mx = -INFINITY;
#pragma unroll
        for (int k = 0; k < 5; k++) {
            int idx = lane + 32 * k;
            v[k] = (idx < ATT) ? g_attn[idx] : -INFINITY;
            mx = fmaxf(mx, v[k]);
        }
        mx = wredmax(mx);
        float s = 0.f;
#pragma unroll
        for (int k = 0; k < 5; k++) {
            int idx = lane + 32 * k;
            if (idx < ATT) {
                float e = expf(v[k] - mx);
                sm->e[idx] = e;
                s += e;
            }
        }
        s = wredsum(s);
        if (lane == 0) sm->bf[0] = 1.f / s;
    }
    __syncthreads();

    int j = (int)blockIdx.x * 32 + lane;
    float acc = 0.f;
    for (int t = wib; t < ATT; t += WPB)
        acc += sm->e[t] * g_enc_out[t * H + j];
    sm->part[wib][lane] = acc;
    __syncthreads();
    if (wib == 0) {
        float a = 0.f;
#pragma unroll
        for (int w = 0; w < WPB; w++) a += sm->part[w][lane];
        g_ctx[j] = a * sm->bf[0];
    }
}

// comb = relu(comb_W @ [emb; ctx] + b): one warp per row
__device__ __forceinline__ void comb_phase(
    const float* __restrict__ comb_W, const float* __restrict__ comb_b,
    const float* __restrict__ dec_emb)
{
    int wib = threadIdx.x >> 5;
    int lane = threadIdx.x & 31;
    if (wib >= 7) return;
    int row = wib * GRID + (int)blockIdx.x;
    if (row >= H) return;
    int tok = g_tok;
    const float4* W  = (const float4*)(comb_W + (size_t)row * 2 * H);
    const float4* e4 = (const float4*)(dec_emb + (size_t)tok * H);
    const float4* c4 = (const float4*)g_ctx;
    float a = 0.f;
#pragma unroll 4
    for (int k = lane; k < H4; k += 32) a += dot4(W[k], e4[k]);
#pragma unroll 4
    for (int k = lane; k < H4; k += 32) a += dot4(W[k + H4], c4[k]);
    a = wredsum(a);
    if (lane == 0) {
        a += comb_b[row];
        g_comb[row] = fmaxf(a, 0.f);
    }
}

// logits GEMV on bf16 weights: split residency — slots 0..5 via __ldg stay
// L2-resident (29MB), slots 6..13 via __ldcs stream from DRAM (36MB) without
// evicting the GRU/comb weights. 2 resident + 2 streamed rows interleaved
// per iteration so DRAM streaming overlaps L2-served loads.
__device__ __forceinline__ void logits_phase(
    const float* __restrict__ out_b, const float* __restrict__ h, Smem* sm)
{
    int tid = threadIdx.x, lane = tid & 31, wib = tid >> 5;
    int gw = (int)blockIdx.x * WPB + wib;

    if (tid < WPB * MAXSLOT) sm->slot[tid] = -INFINITY;
    __syncthreads();

    // h cached: hv[2i],hv[2i+1] cover elements (lane+32i)*8 .. +7
    const float4* h4 = (const float4*)h;
    float4 hv[8];
#pragma unroll
    for (int i = 0; i < 4; i++) {
        hv[2*i]   = h4[(lane + 32*i) * 2];
        hv[2*i+1] = h4[(lane + 32*i) * 2 + 1];
    }

    // rows for slots n=0..12 are always in-bounds (gw + 12*NWARPS < 32000)
#pragma unroll 1
    for (int it = 0; it < 3; it++) {
        int ra0 = gw + (2*it)     * NWARPS;   // resident
        int ra1 = gw + (2*it + 1) * NWARPS;   // resident
        int rb0 = gw + (6 + 2*it) * NWARPS;   // streamed
        int rb1 = gw + (7 + 2*it) * NWARPS;   // streamed
        const uint4* WA0 = (const uint4*)(g_wbf + (size_t)ra0 * H);
        const uint4* WA1 = (const uint4*)(g_wbf + (size_t)ra1 * H);
        const uint4* WB0 = (const uint4*)(g_wbf + (size_t)rb0 * H);
        const uint4* WB1 = (const uint4*)(g_wbf + (size_t)rb1 * H);
        float a0 = 0.f, a1 = 0.f, b0 = 0.f, b1 = 0.f;
#pragma unroll
        for (int i = 0; i < 4; i++) {
            uint4 wa0 = __ldg (&WA0[lane + 32 * i]);
            uint4 wa1 = __ldg (&WA1[lane + 32 * i]);
            uint4 wb0 = __ldcs(&WB0[lane + 32 * i]);
            uint4 wb1 = __ldcs(&WB1[lane + 32 * i]);
            a0 += bfdot8(wa0, hv[2*i], hv[2*i+1]);
            a1 += bfdot8(wa1, hv[2*i], hv[2*i+1]);
            b0 += bfdot8(wb0, hv[2*i], hv[2*i+1]);
            b1 += bfdot8(wb1, hv[2*i], hv[2*i+1]);
        }
        a0 = wredsum(a0);
        a1 = wredsum(a1);
        b0 = wredsum(b0);
        b1 = wredsum(b1);
        if (lane == 0) {
            a0 += out_b[ra0];  g_logits[ra0] = a0;  sm->slot[wib * MAXSLOT + 2*it]     = a0;
            a1 += out_b[ra1];  g_logits[ra1] = a1;  sm->slot[wib * MAXSLOT + 2*it + 1] = a1;
            b0 += out_b[rb0];  g_logits[rb0] = b0;  sm->slot[wib * MAXSLOT + 6 + 2*it] = b0;
            b1 += out_b[rb1];  g_logits[rb1] = b1;  sm->slot[wib * MAXSLOT + 7 + 2*it] = b1;
        }
    }
    // tail: n = 12 (always valid) and n = 13 (conditional), both streamed
    {
        int r0 = gw + 12 * NWARPS;
        int r1 = gw + 13 * NWARPS;
        bool ok1 = (r1 < VOUT);
        const uint4* W0 = (const uint4*)(g_wbf + (size_t)r0 * H);
        const uint4* W1 = (const uint4*)(g_wbf + (size_t)(ok1 ? r1 : r0) * H);
        float a0 = 0.f, a1 = 0.f;
#pragma unroll
        for (int i = 0; i < 4; i++) {
            uint4 w0 = __ldcs(&W0[lane + 32 * i]);
            uint4 w1 = __ldcs(&W1[lane + 32 * i]);
            a0 += bfdot8(w0, hv[2*i], hv[2*i+1]);
            a1 += bfdot8(w1, hv[2*i], hv[2*i+1]);
        }
        a0 = wredsum(a0);
        a1 = wredsum(a1);
        if (lane == 0) {
            a0 += out_b[r0];  g_logits[r0] = a0;  sm->slot[wib * MAXSLOT + 12] = a0;
            if (ok1) {
                a1 += out_b[r1];  g_logits[r1] = a1;  sm->slot[wib * MAXSLOT + 13] = a1;
            }
        }
    }

    // per-warp top-4 scan (lane0, off the hot loop)
    if (lane == 0) {
        unsigned long long c0 = 0, c1 = 0, c2 = 0, c3 = 0;
#pragma unroll
        for (int n = 0; n < MAXSLOT; n++) {
            int row = gw + n * NWARPS;
            if (row < VOUT) {
                unsigned long long p = packf(sm->slot[wib * MAXSLOT + n], row);
                top4_ins(c0, c1, c2, c3, p);
            }
        }
        sm->wtop[wib][0] = c0; sm->wtop[wib][1] = c1;
        sm->wtop[wib][2] = c2; sm->wtop[wib][3] = c3;
    }
    __syncthreads();

    // warp0: pop-merge 16 warp lists -> CTA top-4
    if (wib == 0) {
        unsigned long long a0 = 0, a1 = 0, a2 = 0, a3 = 0;
        if (lane < WPB) {
            a0 = sm->wtop[lane][0]; a1 = sm->wtop[lane][1];
            a2 = sm->wtop[lane][2]; a3 = sm->wtop[lane][3];
        }
        int pos = 0;
        unsigned long long t[4];
#pragma unroll
        for (int k = 0; k < 4; k++) {
            unsigned long long head = (pos == 0) ? a0 : (pos == 1) ? a1 :
                                      (pos == 2) ? a2 : (pos == 3) ? a3 : 0ull;
            unsigned long long m = wredmaxu64(head);
            t[k] = m;
            if (head == m && pos < 4) pos++;
        }
        if (lane == 0) {
#pragma unroll
            for (int k = 0; k < 4; k++) g_ptop[blockIdx.x][k] = t[k];
            sm->bu = t[0];
        }
    }
    __syncthreads();

    // CTA sumexp wrt CTA max
    float m = unpack_max(sm->bu);
    float e = (tid < WPB * MAXSLOT) ? expf(sm->slot[tid] - m) : 0.f;
    sm->red[tid] = e; __syncthreads();
#pragma unroll
    for (int s = BLOCK / 2; s > 0; s >>= 1) {
        if (tid < s) sm->red[tid] += sm->red[tid + s];
        __syncthreads();
    }
    if (tid == 0) g_psum[blockIdx.x] = sm->red[0];
}

// global top-4 merge + lse; fp32 recheck of top-4 for exact argmax;
// write logp row; fuse next-step attention-logit prep
__device__ __forceinline__ void out_phase(
    float* __restrict__ out, int step,
    const float* __restrict__ out_W, const float* __restrict__ out_b,
    const float* __restrict__ attn_W, const float* __restrict__ attn_b,
    const float* __restrict__ dec_emb, const float* __restrict__ h, Smem* sm)
{
    int tid = threadIdx.x, lane = tid & 31, wib = tid >> 5;

    if (wib == 0) {
        // per-lane top-4 over its CTAs
        unsigned long long c0 = 0, c1 = 0, c2 = 0, c3 = 0;
        for (int cc = lane; cc < GRID; cc += 32) {
#pragma unroll
            for (int k = 0; k < 4; k++)
                top4_ins(c0, c1, c2, c3, g_ptop[cc][k]);
        }
        // pop-merge across lanes -> global top-4
        int pos = 0;
        unsigned long long t[4];
#pragma unroll
        for (int k = 0; k < 4; k++) {
            unsigned long long head = (pos == 0) ? c0 : (pos == 1) ? c1 :
                                      (pos == 2) ? c2 : (pos == 3) ? c3 : 0ull;
            unsigned long long mm = wredmaxu64(head);
            t[k] = mm;
            if (head == mm && pos < 4) pos++;
        }
        float M = unpack_max(t[0]);
        float S = 0.f;
        for (int cc = lane; cc < GRID; cc += 32)
            S += g_psum[cc] * expf(unpack_max(g_ptop[cc][0]) - M);
        S = wredsum(S);
        if (lane == 0) {
#pragma unroll
            for (int k = 0; k < 4; k++) sm->top4[k] = t[k];
            sm->bf[0] = M + logf(S);
        }
    }
    __syncthreads();
    float lse = sm->bf[0];

    // write logp row (bf16-based logits, fp32 lse)
    int g = (int)blockIdx.x * BLOCK + tid;
    if (g < VOUT) out[(size_t)step * VOUT + g] = g_logits[g] - lse;

    // fp32 recheck of the 4 candidates (warps 0..3, one row each)
    if (wib < 4) {
        int rk = unpack_idx(sm->top4[wib]);
        const float4* W = (const float4*)(out_W + (size_t)rk * H);
        const float4* h4 = (const float4*)h;
        float a = 0.f;
#pragma unroll 4
        for (int k = lane; k < H4; k += 32) a += dot4(W[k], h4[k]);
        a = wredsum(a);
        if (lane == 0) sm->cand[wib] = packf(a + out_b[rk], rk);
    }
    __syncthreads();
    unsigned long long w = sm->cand[0];
#pragma unroll
    for (int k = 1; k < 4; k++) if (sm->cand[k] > w) w = sm->cand[k];
    int tok = unpack_idx(w);

    // next-step attention logits: two-warp split per CTA row
    if ((int)blockIdx.x < ATT) {
        int r = (int)blockIdx.x;
        if (wib == 0) {        // emb half
            const float4* W  = (const float4*)(attn_W + (size_t)r * 2 * H);
            const float4* e4 = (const float4*)(dec_emb + (size_t)tok * H);
            float a = 0.f;
#pragma unroll 4
            for (int k = lane; k < H4; k += 32) a += dot4(W[k], e4[k]);
            a = wredsum(a);
            if (lane == 0) sm->bf[1] = a;
        } else if (wib == 8) { // h half
            const float4* W  = (const float4*)(attn_W + (size_t)r * 2 * H + H);
            const float4* h4 = (const float4*)h;
            float a = 0.f;
#pragma unroll 4
            for (int k = lane; k < H4; k += 32) a += dot4(W[k], h4[k]);
            a = wredsum(a);
            if (lane == 0) sm->bf[2] = a;
        }
        __syncthreads();
        if (tid == 0) g_attn[r] = sm->bf[1] + sm->bf[2] + attn_b[r];
    }
    if (blockIdx.x == 0 && tid == 0) g_tok = tok;
}

// ---------------- the single persistent kernel ----------------
__global__ void __launch_bounds__(BLOCK, 1) k_all(
    const int* __restrict__ tokens,
    const float* __restrict__ enc_emb,
    const float* __restrict__ enc_Wih, const float* __restrict__ enc_Whh,
    const float* __restrict__ enc_bih, const float* __restrict__ enc_bhh,
    const float* __restrict__ dec_emb,
    const float* __restrict__ attn_W, const float* __restrict__ attn_b,
    const float* __restrict__ comb_W, const float* __restrict__ comb_b,
    const float* __restrict__ dec_Wih, const float* __restrict__ dec_Whh,
    const float* __restrict__ dec_bih, const float* __restrict__ dec_bhh,
    const float* __restrict__ out_W, const float* __restrict__ out_b,
    float* __restrict__ out)
{
    __shared__ Smem sm;
    int tid = threadIdx.x;

    // one-time: convert out_W to bf16 (grid-stride, vectorized).
    // Read fp32 evict-first; write bf16 (streamed writes are fine — the
    // resident slice gets re-pulled into L2 by the first decoder step's __ldg).
    {
        const float4* w4 = (const float4*)out_W;
        uint2* dst = (uint2*)g_wbf;
        const int n4 = VOUT * (H / 4);
        for (int i = (int)blockIdx.x * BLOCK + tid; i < n4; i += GRID * BLOCK) {
            float4 v = __ldcs(&w4[i]);
            __nv_bfloat162 lo = __floats2bfloat162_rn(v.x, v.y);
            __nv_bfloat162 hi = __floats2bfloat162_rn(v.z, v.w);
            uint2 o;
            o.x = *(unsigned*)&lo;
            o.y = *(unsigned*)&hi;
            dst[i] = o;
        }
    }

    // init: h0 = 0, padding row of enc_out = 0
    {
        int g = (int)blockIdx.x * BLOCK + tid;
        if (g < H) { g_h[0][g] = 0.f; g_enc_out[ML * H + g] = 0.f; }
    }
    gsync();

    // ---- encoder ----
    for (int t = 0; t < ML; t++) {
        const float* x = enc_emb + (size_t)tokens[t] * H;
        gru_phase(enc_Wih, enc_Whh, enc_bih, enc_bhh, x,
                  g_h[t & 1], g_h[(t & 1) ^ 1], g_enc_out + (size_t)t * H);
        gsync();
    }
    // final encoder hidden in g_h[0]

    // ---- decoder prep (tok = SOS = 0): attention logits (two-warp split) ----
    if ((int)blockIdx.x < ATT) {
        int r = (int)blockIdx.x;
        int wib = tid >> 5, lane = tid & 31;
        if (wib == 0) {
            const float4* W  = (const float4*)(attn_W + (size_t)r * 2 * H);
            const float4* e4 = (const float4*)dec_emb;  // row 0 (SOS)
            float a = 0.f;
#pragma unroll 4
            for (int k = lane; k < H4; k += 32) a += dot4(W[k], e4[k]);
            a = wredsum(a);
            if (lane == 0) sm.bf[1] = a;
        } else if (wib == 8) {
            const float4* W  = (const float4*)(attn_W + (size_t)r * 2 * H + H);
            const float4* h4 = (const float4*)g_h[0];
            float a = 0.f;
#pragma unroll 4
            for (int k = lane; k < H4; k += 32) a += dot4(W[k], h4[k]);
            a = wredsum(a);
            if (lane == 0) sm.bf[2] = a;
        }
        __syncthreads();
        if (tid == 0) g_attn[r] = sm.bf[1] + sm.bf[2] + attn_b[r];
    }
    if (blockIdx.x == 0 && tid == 0) g_tok = 0;
    gsync();

    // ---- decoder ----
    for (int s = 0; s < ML; s++) {
        const float* hc = g_h[s & 1];
        float* hn = g_h[(s & 1) ^ 1];

        ctx_phase(&sm);                                        gsync();
        comb_phase(comb_W, comb_b, dec_emb);                   gsync();
        gru_phase(dec_Wih, dec_Whh, dec_bih, dec_bhh,
                  g_comb, hc, hn, nullptr);                    gsync();
        logits_phase(out_b, hn, &sm);                          gsync();
        out_phase(out, s, out_W, out_b, attn_W, attn_b,
                  dec_emb, hn, &sm);                           gsync();
    }
}

// ---------------- host launcher ----------------
extern "C" void kernel_launch(void* const* d_in, const int* in_sizes, int n_in,
                              void* d_out, int out_size)
{
    const int*   tokens  = (const int*)  d_in[0];
    // d_in[1] = max_length (compile-time ML=128)
    const float* enc_emb = (const float*)d_in[2];
    const float* enc_Wih = (const float*)d_in[3];
    const float* enc_Whh = (const float*)d_in[4];
    const float* enc_bih = (const float*)d_in[5];
    const float* enc_bhh = (const float*)d_in[6];
    const float* dec_emb = (const float*)d_in[7];
    const float* attn_W  = (const float*)d_in[8];
    const float* attn_b  = (const float*)d_in[9];
    const float* comb_W  = (const float*)d_in[10];
    const float* comb_b  = (const float*)d_in[11];
    const float* dec_Wih = (const float*)d_in[12];
    const float* dec_Whh = (const float*)d_in[13];
    const float* dec_bih = (const float*)d_in[14];
    const float* dec_bhh = (const float*)d_in[15];
    const float* out_W   = (const float*)d_in[16];
    const float* out_b   = (const float*)d_in[17];
    float* out = (float*)d_out;

    k_all<<<GRID, BLOCK>>>(tokens, enc_emb, enc_Wih, enc_Whh, enc_bih, enc_bhh,
                           dec_emb, attn_W, attn_b, comb_W, comb_b,
                           dec_Wih, dec_Whh, dec_bih, dec_bhh,
                           out_W, out_b, out);
}

// round 9
// speedup vs baseline: 1.1856x; 1.0458x over previous
#include <cuda_runtime.h>
#include <cuda_bf16.h>
#include <math.h>

#define H      1024
#define H4     256          // H/4
#define VOUT   32000
#define ML     128
#define ATT    129          // ML + 1
#define GRID   148
#define BLOCK  512
#define WPB    (BLOCK/32)   // 16 warps per block
#define NWARPS (GRID*WPB)   // 2368
#define MAXSLOT 14          // max rows per warp
// slots 0..7 (first 18944 rows, 38.9MB) stay L2-resident via __ldg;
// slots 8..13 (26.7MB) stream from DRAM via __ldcs.

// ---------------- device scratch (static, no allocation) ----------------
__device__ float g_h[2][H];
__device__ float g_enc_out[ATT * H];
__device__ float g_attn[ATT];
__device__ float g_ctx[H];
__device__ float g_comb[H];
__device__ float g_logits[VOUT];
__device__ unsigned long long g_ptop[GRID][4]; // per-CTA top-4 packed (bf16-based)
__device__ float g_psum[GRID];                 // per-CTA sumexp wrt its own max
__device__ int g_tok;
__device__ __nv_bfloat16 g_wbf[(size_t)VOUT * H];  // 64MB bf16 copy of out_W

__device__ unsigned g_bar_count = 0;
__device__ unsigned g_bar_gen   = 0;

// ---------------- helpers ----------------
__device__ __forceinline__ float wredsum(float v) {
#pragma unroll
    for (int o = 16; o > 0; o >>= 1) v += __shfl_xor_sync(0xffffffffu, v, o);
    return v;
}
__device__ __forceinline__ float wredmax(float v) {
#pragma unroll
    for (int o = 16; o > 0; o >>= 1) v = fmaxf(v, __shfl_xor_sync(0xffffffffu, v, o));
    return v;
}
__device__ __forceinline__ unsigned long long wredmaxu64(unsigned long long v) {
#pragma unroll
    for (int o = 16; o > 0; o >>= 1) {
        unsigned long long q = __shfl_xor_sync(0xffffffffu, v, o);
        if (q > v) v = q;
    }
    return v;
}

__device__ __forceinline__ unsigned long long packf(float v, int idx) {
    unsigned u = __float_as_uint(v);
    u = (u & 0x80000000u) ? ~u : (u | 0x80000000u);   // totally ordered float bits
    return ((unsigned long long)u << 32) | (unsigned)(~(unsigned)idx); // tie -> lowest idx
}
__device__ __forceinline__ float unpack_max(unsigned long long p) {
    unsigned u = (unsigned)(p >> 32);
    unsigned b = (u & 0x80000000u) ? (u & 0x7fffffffu) : ~u;
    return __uint_as_float(b);
}
__device__ __forceinline__ int unpack_idx(unsigned long long p) {
    return (int)(~(unsigned)(p & 0xffffffffu));
}

__device__ __forceinline__ float dot4(float4 a, float4 b) {
    return a.x * b.x + a.y * b.y + a.z * b.z + a.w * b.w;
}

// 8-elem bf16 dot against two float4 halves
__device__ __forceinline__ float bfdot8(uint4 w, float4 a, float4 b) {
    float2 p0 = __bfloat1622float2(*(__nv_bfloat162*)&w.x);
    float2 p1 = __bfloat1622float2(*(__nv_bfloat162*)&w.y);
    float2 p2 = __bfloat1622float2(*(__nv_bfloat162*)&w.z);
    float2 p3 = __bfloat1622float2(*(__nv_bfloat162*)&w.w);
    return p0.x*a.x + p0.y*a.y + p1.x*a.z + p1.y*a.w
         + p2.x*b.x + p2.y*b.y + p3.x*b.z + p3.y*b.w;
}

// insert p into descending top-4 (c0>=c1>=c2>=c3)
__device__ __forceinline__ void top4_ins(unsigned long long& c0, unsigned long long& c1,
                                         unsigned long long& c2, unsigned long long& c3,
                                         unsigned long long p) {
    if (p > c0)      { c3 = c2; c2 = c1; c1 = c0; c0 = p; }
    else if (p > c1) { c3 = c2; c2 = c1; c1 = p; }
    else if (p > c2) { c3 = c2; c2 = p; }
    else if (p > c3) { c3 = p; }
}

// ---------------- grid-wide barrier (CG grid.sync pattern) ----------------
__device__ __forceinline__ unsigned ld_acq(unsigned* p) {
    unsigned v;
    asm volatile("ld.acquire.gpu.u32 %0, [%1];" : "=r"(v) : "l"(p) : "memory");
    return v;
}
__device__ __forceinline__ void st_rel(unsigned* p, unsigned v) {
    asm volatile("st.release.gpu.u32 [%0], %1;" :: "l"(p), "r"(v) : "memory");
}

__device__ __forceinline__ void gsync() {
    __syncthreads();
    if (threadIdx.x == 0) {
        unsigned gen = ld_acq(&g_bar_gen);
        __threadfence();
        if (atomicAdd(&g_bar_count, 1) == GRID - 1) {
            g_bar_count = 0;
            st_rel(&g_bar_gen, gen + 1);
        } else {
            while (ld_acq(&g_bar_gen) == gen) { }
        }
    }
    __syncthreads();
}

// ---------------- shared-memory layout ----------------
struct Smem {
    float e[ATT];                 // attention softmax weights
    float part[WPB][33];          // ctx partial sums (padded)
    float slot[WPB * MAXSLOT];    // raw logits per warp slot
    float red[BLOCK];             // reduction scratch
    unsigned long long wtop[WPB][4];
    unsigned long long top4[4];
    unsigned long long cand[4];
    float bf[4];                  // scalar broadcasts
    unsigned long long bu;
};

// ---------------- phases ----------------

// GRU step: warp w<7 handles row = w*GRID + cta, all 6 dots.
__device__ __forceinline__ void gru_phase(
    const float* __restrict__ Wih, const float* __restrict__ Whh,
    const float* __restrict__ bih, const float* __restrict__ bhh,
    const float* __restrict__ x, const float* __restrict__ h,
    float* __restrict__ ho, float* __restrict__ enc_row)
{
    int wib = threadIdx.x >> 5;
    int lane = threadIdx.x & 31;
    if (wib >= 7) return;
    int row = wib * GRID + (int)blockIdx.x;
    if (row >= H) return;

    const float4* x4 = (const float4*)x;
    const float4* h4 = (const float4*)h;
    const float4* Wir = (const float4*)(Wih + (size_t)row * H);
    const float4* Wiz = (const float4*)(Wih + (size_t)(row + H) * H);
    const float4* Win = (const float4*)(Wih + (size_t)(row + 2 * H) * H);
    const float4* Whr = (const float4*)(Whh + (size_t)row * H);
    const float4* Whz = (const float4*)(Whh + (size_t)(row + H) * H);
    const float4* Whn = (const float4*)(Whh + (size_t)(row + 2 * H) * H);

    float ir = 0.f, iz = 0.f, inn = 0.f, hr = 0.f, hz = 0.f, hn = 0.f;
#pragma unroll 4
    for (int k = lane; k < H4; k += 32) {
        float4 xv = x4[k], hv = h4[k];
        ir  += dot4(Wir[k], xv);
        iz  += dot4(Wiz[k], xv);
        inn += dot4(Win[k], xv);
        hr  += dot4(Whr[k], hv);
        hz  += dot4(Whz[k], hv);
        hn  += dot4(Whn[k], hv);
    }
    ir = wredsum(ir);  iz = wredsum(iz);  inn = wredsum(inn);
    hr = wredsum(hr);  hz = wredsum(hz);  hn  = wredsum(hn);

    if (lane == 0) {
        ir  += bih[row];          hr += bhh[row];
        iz  += bih[row + H];      hz += bhh[row + H];
        inn += bih[row + 2 * H];  hn += bhh[row + 2 * H];
        float r = 1.f / (1.f + expf(-(ir + hr)));
        float z = 1.f / (1.f + expf(-(iz + hz)));
        float n = tanhf(inn + r * hn);
        float hnew = (1.f - z) * n + z * h[row];
        ho[row] = hnew;
        if (enc_row) enc_row[row] = hnew;
    }
}

// attention softmax + context. CTAs 0..31 each produce 32 ctx elements.
__device__ __forceinline__ void ctx_phase(Smem* sm)
{
    if ((int)blockIdx.x >= 32) return;
    int wib = threadIdx.x >> 5, lane = threadIdx.x & 31;

    if (wib == 0) {
        float v[5];
        float mx = -INFINITY;
#pragma unroll
        for (int k = 0; k < 5; k++) {
            int idx = lane + 32 * k;
            v[k] = (idx < ATT) ? g_attn[idx] : -INFINITY;
            mx = fmaxf(mx, v[k]);
        }
        mx = wredmax(mx);
        float s = 0.f;
#pragma unroll
        for (int k = 0; k < 5; k++) {
            int idx = lane + 32 * k;
            if (idx < ATT) {
                float e = expf(v[k] - mx);
                sm->e[idx] = e;
                s += e;
            }
        }
        s = wredsum(s);
        if (lane == 0) sm->bf[0] = 1.f / s;
    }
    __syncthreads();

    int j = (int)blockIdx.x * 32 + lane;
    float acc = 0.f;
    for (int t = wib; t < ATT; t += WPB)
        acc += sm->e[t] * g_enc_out[t * H + j];
    sm->part[wib][lane] = acc;
    __syncthreads();
    if (wib == 0) {
        float a = 0.f;
#pragma unroll
        for (int w = 0; w < WPB; w++) a += sm->part[w][lane];
        g_ctx[j] = a * sm->bf[0];
    }
}

// comb = relu(comb_W @ [emb; ctx] + b): one warp per row, deep unroll for MLP
__device__ __forceinline__ void comb_phase(
    const float* __restrict__ comb_W, const float* __restrict__ comb_b,
    const float* __restrict__ dec_emb)
{
    int wib = threadIdx.x >> 5;
    int lane = threadIdx.x & 31;
    if (wib >= 7) return;
    int row = wib * GRID + (int)blockIdx.x;
    if (row >= H) return;
    int tok = g_tok;
    const float4* W  = (const float4*)(comb_W + (size_t)row * 2 * H);
    const float4* e4 = (const float4*)(dec_emb + (size_t)tok * H);
    const float4* c4 = (const float4*)g_ctx;
    float a = 0.f;
#pragma unroll 8
    for (int k = lane; k < H4; k += 32) a += dot4(W[k], e4[k]);
#pragma unroll 8
    for (int k = lane; k < H4; k += 32) a += dot4(W[k + H4], c4[k]);
    a = wredsum(a);
    if (lane == 0) {
        a += comb_b[row];
        g_comb[row] = fmaxf(a, 0.f);
    }
}

// one warp-GEMV row quad: policies are compile-time (R = # of __ldg rows of the 4)
template<int NRES>
__device__ __forceinline__ void logits_quad(
    int r0, int r1, int r2, int r3, const float4* hv,
    const float* __restrict__ out_b, float* slotp,
    int s0, int s1, int s2, int s3, int lane)
{
    const uint4* W0 = (const uint4*)(g_wbf + (size_t)r0 * H);
    const uint4* W1 = (const uint4*)(g_wbf + (size_t)r1 * H);
    const uint4* W2 = (const uint4*)(g_wbf + (size_t)r2 * H);
    const uint4* W3 = (const uint4*)(g_wbf + (size_t)r3 * H);
    float a0 = 0.f, a1 = 0.f, a2 = 0.f, a3 = 0.f;
#pragma unroll
    for (int i = 0; i < 4; i++) {
        uint4 w0 = (NRES > 0) ? __ldg(&W0[lane + 32*i]) : __ldcs(&W0[lane + 32*i]);
        uint4 w1 = (NRES > 1) ? __ldg(&W1[lane + 32*i]) : __ldcs(&W1[lane + 32*i]);
        uint4 w2 = (NRES > 2) ? __ldg(&W2[lane + 32*i]) : __ldcs(&W2[lane + 32*i]);
        uint4 w3 = (NRES > 3) ? __ldg(&W3[lane + 32*i]) : __ldcs(&W3[lane + 32*i]);
        a0 += bfdot8(w0, hv[2*i], hv[2*i+1]);
        a1 += bfdot8(w1, hv[2*i], hv[2*i+1]);
        a2 += bfdot8(w2, hv[2*i], hv[2*i+1]);
        a3 += bfdot8(w3, hv[2*i], hv[2*i+1]);
    }
    a0 = wredsum(a0);
    a1 = wredsum(a1);
    a2 = wredsum(a2);
    a3 = wredsum(a3);
    if (lane == 0) {
        a0 += out_b[r0];  g_logits[r0] = a0;  slotp[s0] = a0;
        a1 += out_b[r1];  g_logits[r1] = a1;  slotp[s1] = a1;
        a2 += out_b[r2];  g_logits[r2] = a2;  slotp[s2] = a2;
        a3 += out_b[r3];  g_logits[r3] = a3;  slotp[s3] = a3;
    }
}

// logits GEMV on bf16 weights: split residency — slots 0..7 via __ldg stay
// L2-resident (38.9MB), slots 8..13 via __ldcs stream from DRAM (26.7MB),
// interleaved so DRAM streaming overlaps L2-served loads.
__device__ __forceinline__ void logits_phase(
    const float* __restrict__ out_b, const float* __restrict__ h, Smem* sm)
{
    int tid = threadIdx.x, lane = tid & 31, wib = tid >> 5;
    int gw = (int)blockIdx.x * WPB + wib;

    if (tid < WPB * MAXSLOT) sm->slot[tid] = -INFINITY;
    __syncthreads();

    // h cached: hv[2i],hv[2i+1] cover elements (lane+32i)*8 .. +7
    const float4* h4 = (const float4*)h;
    float4 hv[8];
#pragma unroll
    for (int i = 0; i < 4; i++) {
        hv[2*i]   = h4[(lane + 32*i) * 2];
        hv[2*i+1] = h4[(lane + 32*i) * 2 + 1];
    }
    float* slotp = sm->slot + wib * MAXSLOT;

    // rows for slots n=0..12 are always in-bounds (gw + 12*NWARPS < 32000)
    // resident slots: 0..7 ; streamed slots: 8..13
    logits_quad<2>(gw + 0*NWARPS, gw + 1*NWARPS, gw +  8*NWARPS, gw +  9*NWARPS,
                   hv, out_b, slotp, 0, 1, 8, 9, lane);
    logits_quad<2>(gw + 2*NWARPS, gw + 3*NWARPS, gw + 10*NWARPS, gw + 11*NWARPS,
                   hv, out_b, slotp, 2, 3, 10, 11, lane);
    logits_quad<3>(gw + 4*NWARPS, gw + 5*NWARPS, gw +  6*NWARPS, gw + 12*NWARPS,
                   hv, out_b, slotp, 4, 5, 6, 12, lane);
    // tail: slot 7 (resident, always valid) + slot 13 (streamed, conditional)
    {
        int r0 = gw + 7 * NWARPS;
        int r1 = gw + 13 * NWARPS;
        bool ok1 = (r1 < VOUT);
        const uint4* W0 = (const uint4*)(g_wbf + (size_t)r0 * H);
        const uint4* W1 = (const uint4*)(g_wbf + (size_t)(ok1 ? r1 : r0) * H);
        float a0 = 0.f, a1 = 0.f;
#pragma unroll
        for (int i = 0; i < 4; i++) {
            uint4 w0 = __ldg (&W0[lane + 32 * i]);
            uint4 w1 = __ldcs(&W1[lane + 32 * i]);
            a0 += bfdot8(w0, hv[2*i], hv[2*i+1]);
            a1 += bfdot8(w1, hv[2*i], hv[2*i+1]);
        }
        a0 = wredsum(a0);
        a1 = wredsum(a1);
        if (lane == 0) {
            a0 += out_b[r0];  g_logits[r0] = a0;  slotp[7] = a0;
            if (ok1) {
                a1 += out_b[r1];  g_logits[r1] = a1;  slotp[13] = a1;
            }
        }
    }

    // per-warp top-4 scan (lane0, off the hot loop)
    if (lane == 0) {
        unsigned long long c0 = 0, c1 = 0, c2 = 0, c3 = 0;
#pragma unroll
        for (int n = 0; n < MAXSLOT; n++) {
            int row = gw + n * NWARPS;
            if (row < VOUT) {
                unsigned long long p = packf(slotp[n], row);
                top4_ins(c0, c1, c2, c3, p);
            }
        }
        sm->wtop[wib][0] = c0; sm->wtop[wib][1] = c1;
        sm->wtop[wib][2] = c2; sm->wtop[wib][3] = c3;
    }
    __syncthreads();

    // warp0: pop-merge 16 warp lists -> CTA top-4
    if (wib == 0) {
        unsigned long long a0 = 0, a1 = 0, a2 = 0, a3 = 0;
        if (lane < WPB) {
            a0 = sm->wtop[lane][0]; a1 = sm->wtop[lane][1];
            a2 = sm->wtop[lane][2]; a3 = sm->wtop[lane][3];
        }
        int pos = 0;
        unsigned long long t[4];
#pragma unroll
        for (int k = 0; k < 4; k++) {
            unsigned long long head = (pos == 0) ? a0 : (pos == 1) ? a1 :
                                      (pos == 2) ? a2 : (pos == 3) ? a3 : 0ull;
            unsigned long long m = wredmaxu64(head);
            t[k] = m;
            if (head == m && pos < 4) pos++;
        }
        if (lane == 0) {
#pragma unroll
            for (int k = 0; k < 4; k++) g_ptop[blockIdx.x][k] = t[k];
            sm->bu = t[0];
        }
    }
    __syncthreads();

    // CTA sumexp wrt CTA max: warp-level (slots 0..223 covered by warps 0..6)
    {
        float m = unpack_max(sm->bu);
        float e = (tid < WPB * MAXSLOT) ? expf(sm->slot[tid] - m) : 0.f;
        e = wredsum(e);
        if (lane == 0) sm->red[wib] = e;
        __syncthreads();
        if (tid == 0) {
            float S = 0.f;
#pragma unroll
            for (int i = 0; i < 7; i++) S += sm->red[i];
            g_psum[blockIdx.x] = S;
        }
    }
}

// global top-4 merge + lse; fp32 recheck of top-4 for exact argmax;
// write logp row; fuse next-step attention-logit prep
__device__ __forceinline__ void out_phase(
    float* __restrict__ out, int step,
    const float* __restrict__ out_W, const float* __restrict__ out_b,
    const float* __restrict__ attn_W, const float* __restrict__ attn_b,
    const float* __restrict__ dec_emb, const float* __restrict__ h, Smem* sm)
{
    int tid = threadIdx.x, lane = tid & 31, wib = tid >> 5;

    if (wib == 0) {
        // per-lane top-4 over its CTAs
        unsigned long long c0 = 0, c1 = 0, c2 = 0, c3 = 0;
        for (int cc = lane; cc < GRID; cc += 32) {
#pragma unroll
            for (int k = 0; k < 4; k++)
                top4_ins(c0, c1, c2, c3, g_ptop[cc][k]);
        }
        // pop-merge across lanes -> global top-4
        int pos = 0;
        unsigned long long t[4];
#pragma unroll
        for (int k = 0; k < 4; k++) {
            unsigned long long head = (pos == 0) ? c0 : (pos == 1) ? c1 :
                                      (pos == 2) ? c2 : (pos == 3) ? c3 : 0ull;
            unsigned long long mm = wredmaxu64(head);
            t[k] = mm;
            if (head == mm && pos < 4) pos++;
        }
        float M = unpack_max(t[0]);
        float S = 0.f;
        for (int cc = lane; cc < GRID; cc += 32)
            S += g_psum[cc] * expf(unpack_max(g_ptop[cc][0]) - M);
        S = wredsum(S);
        if (lane == 0) {
#pragma unroll
            for (int k = 0; k < 4; k++) sm->top4[k] = t[k];
            sm->bf[0] = M + logf(S);
        }
    }
    __syncthreads();
    float lse = sm->bf[0];

    // write logp row (bf16-based logits, fp32 lse)
    int g = (int)blockIdx.x * BLOCK + tid;
    if (g < VOUT) out[(size_t)step * VOUT + g] = g_logits[g] - lse;

    // fp32 recheck of the 4 candidates (warps 0..3, one row each)
    if (wib < 4) {
        int rk = unpack_idx(sm->top4[wib]);
        const float4* W = (const float4*)(out_W + (size_t)rk * H);
        const float4* h4 = (const float4*)h;
        float a = 0.f;
#pragma unroll 4
        for (int k = lane; k < H4; k += 32) a += dot4(W[k], h4[k]);
        a = wredsum(a);
        if (lane == 0) sm->cand[wib] = packf(a + out_b[rk], rk);
    }
    __syncthreads();
    unsigned long long w = sm->cand[0];
#pragma unroll
    for (int k = 1; k < 4; k++) if (sm->cand[k] > w) w = sm->cand[k];
    int tok = unpack_idx(w);

    // next-step attention logits: two-warp split per CTA row
    if ((int)blockIdx.x < ATT) {
        int r = (int)blockIdx.x;
        if (wib == 0) {        // emb half
            const float4* W  = (const float4*)(attn_W + (size_t)r * 2 * H);
            const float4* e4 = (const float4*)(dec_emb + (size_t)tok * H);
            float a = 0.f;
#pragma unroll 4
            for (int k = lane; k < H4; k += 32) a += dot4(W[k], e4[k]);
            a = wredsum(a);
            if (lane == 0) sm->bf[1] = a;
        } else if (wib == 8) { // h half
            const float4* W  = (const float4*)(attn_W + (size_t)r * 2 * H + H);
            const float4* h4 = (const float4*)h;
            float a = 0.f;
#pragma unroll 4
            for (int k = lane; k < H4; k += 32) a += dot4(W[k], h4[k]);
            a = wredsum(a);
            if (lane == 0) sm->bf[2] = a;
        }
        __syncthreads();
        if (tid == 0) g_attn[r] = sm->bf[1] + sm->bf[2] + attn_b[r];
    }
    if (blockIdx.x == 0 && tid == 0) g_tok = tok;
}

// ---------------- the single persistent kernel ----------------
__global__ void __launch_bounds__(BLOCK, 1) k_all(
    const int* __restrict__ tokens,
    const float* __restrict__ enc_emb,
    const float* __restrict__ enc_Wih, const float* __restrict__ enc_Whh,
    const float* __restrict__ enc_bih, const float* __restrict__ enc_bhh,
    const float* __restrict__ dec_emb,
    const float* __restrict__ attn_W, const float* __restrict__ attn_b,
    const float* __restrict__ comb_W, const float* __restrict__ comb_b,
    const float* __restrict__ dec_Wih, const float* __restrict__ dec_Whh,
    const float* __restrict__ dec_bih, const float* __restrict__ dec_bhh,
    const float* __restrict__ out_W, const float* __restrict__ out_b,
    float* __restrict__ out)
{
    __shared__ Smem sm;
    int tid = threadIdx.x;

    // one-time: convert out_W to bf16 (grid-stride, vectorized).
    {
        const float4* w4 = (const float4*)out_W;
        uint2* dst = (uint2*)g_wbf;
        const int n4 = VOUT * (H / 4);
        for (int i = (int)blockIdx.x * BLOCK + tid; i < n4; i += GRID * BLOCK) {
            float4 v = __ldcs(&w4[i]);
            __nv_bfloat162 lo = __floats2bfloat162_rn(v.x, v.y);
            __nv_bfloat162 hi = __floats2bfloat162_rn(v.z, v.w);
            uint2 o;
            o.x = *(unsigned*)&lo;
            o.y = *(unsigned*)&hi;
            dst[i] = o;
        }
    }

    // init: h0 = 0, padding row of enc_out = 0
    {
        int g = (int)blockIdx.x * BLOCK + tid;
        if (g < H) { g_h[0][g] = 0.f; g_enc_out[ML * H + g] = 0.f; }
    }
    gsync();

    // ---- encoder ----
    for (int t = 0; t < ML; t++) {
        const float* x = enc_emb + (size_t)tokens[t] * H;
        gru_phase(enc_Wih, enc_Whh, enc_bih, enc_bhh, x,
                  g_h[t & 1], g_h[(t & 1) ^ 1], g_enc_out + (size_t)t * H);
        gsync();
    }
    // final encoder hidden in g_h[0]

    // ---- decoder prep (tok = SOS = 0): attention logits (two-warp split) ----
    if ((int)blockIdx.x < ATT) {
        int r = (int)blockIdx.x;
        int wib = tid >> 5, lane = tid & 31;
        if (wib == 0) {
            const float4* W  = (const float4*)(attn_W + (size_t)r * 2 * H);
            const float4* e4 = (const float4*)dec_emb;  // row 0 (SOS)
            float a = 0.f;
#pragma unroll 4
            for (int k = lane; k < H4; k += 32) a += dot4(W[k], e4[k]);
            a = wredsum(a);
            if (lane == 0) sm.bf[1] = a;
        } else if (wib == 8) {
            const float4* W  = (const float4*)(attn_W + (size_t)r * 2 * H + H);
            const float4* h4 = (const float4*)g_h[0];
            float a = 0.f;
#pragma unroll 4
            for (int k = lane; k < H4; k += 32) a += dot4(W[k], h4[k]);
            a = wredsum(a);
            if (lane == 0) sm.bf[2] = a;
        }
        __syncthreads();
        if (tid == 0) g_attn[r] = sm.bf[1] + sm.bf[2] + attn_b[r];
    }
    if (blockIdx.x == 0 && tid == 0) g_tok = 0;
    gsync();

    // ---- decoder ----
    for (int s = 0; s < ML; s++) {
        const float* hc = g_h[s & 1];
        float* hn = g_h[(s & 1) ^ 1];

        ctx_phase(&sm);                                        gsync();
        comb_phase(comb_W, comb_b, dec_emb);                   gsync();
        gru_phase(dec_Wih, dec_Whh, dec_bih, dec_bhh,
                  g_comb, hc, hn, nullptr);                    gsync();
        logits_phase(out_b, hn, &sm);                          gsync();
        out_phase(out, s, out_W, out_b, attn_W, attn_b,
                  dec_emb, hn, &sm);                           gsync();
    }
}

// ---------------- host launcher ----------------
extern "C" void kernel_launch(void* const* d_in, const int* in_sizes, int n_in,
                              void* d_out, int out_size)
{
    const int*   tokens  = (const int*)  d_in[0];
    // d_in[1] = max_length (compile-time ML=128)
    const float* enc_emb = (const float*)d_in[2];
    const float* enc_Wih = (const float*)d_in[3];
    const float* enc_Whh = (const float*)d_in[4];
    const float* enc_bih = (const float*)d_in[5];
    const float* enc_bhh = (const float*)d_in[6];
    const float* dec_emb = (const float*)d_in[7];
    const float* attn_W  = (const float*)d_in[8];
    const float* attn_b  = (const float*)d_in[9];
    const float* comb_W  = (const float*)d_in[10];
    const float* comb_b  = (const float*)d_in[11];
    const float* dec_Wih = (const float*)d_in[12];
    const float* dec_Whh = (const float*)d_in[13];
    const float* dec_bih = (const float*)d_in[14];
    const float* dec_bhh = (const float*)d_in[15];
    const float* out_W   = (const float*)d_in[16];
    const float* out_b   = (const float*)d_in[17];
    float* out = (float*)d_out;

    k_all<<<GRID, BLOCK>>>(tokens, enc_emb, enc_Wih, enc_Whh, enc_bih, enc_bhh,
                           dec_emb, attn_W, attn_b, comb_W, comb_b,
                           dec_Wih, dec_Whh, dec_bih, dec_bhh,
                           out_W, out_b, out);
}

// round 10
// speedup vs baseline: 1.2683x; 1.0698x over previous
#include <cuda_runtime.h>
#include <cuda_bf16.h>
#include <math.h>

#define H      1024
#define H4     256          // H/4
#define VOUT   32000
#define ML     128
#define ATT    129          // ML + 1
#define ATTP   160          // padded attention length (multiple of 32)
#define GRID   148
#define BLOCK  512
#define WPB    (BLOCK/32)   // 16 warps per block
#define NWARPS (GRID*WPB)   // 2368
#define MAXSLOT 14          // max rows per warp
// logits slots 0..7 (38.9MB) stay L2-resident via __ldg;
// slots 8..13 (26.7MB) stream from DRAM via __ldcs.

// ---------------- device scratch (static, no allocation) ----------------
__device__ float g_h[2][H];
__device__ float g_enc_T[(size_t)H * ATTP];    // transposed encoder outputs [j][t]
__device__ float g_M[(size_t)H * ATTP];        // M[i][t] = dot(W2[i], enc_out[t])
__device__ float g_attn[ATT];
__device__ float g_comb[H];
__device__ float g_logits[VOUT];
__device__ unsigned long long g_ptop[GRID][4]; // per-CTA top-4 packed (bf16-based)
__device__ float g_psum[GRID];                 // per-CTA sumexp wrt its own max
__device__ int g_tok;
__device__ __nv_bfloat16 g_wbf[(size_t)VOUT * H];  // 64MB bf16 copy of out_W

__device__ unsigned g_bar_count = 0;
__device__ unsigned g_bar_gen   = 0;

// ---------------- helpers ----------------
__device__ __forceinline__ float wredsum(float v) {
#pragma unroll
    for (int o = 16; o > 0; o >>= 1) v += __shfl_xor_sync(0xffffffffu, v, o);
    return v;
}
__device__ __forceinline__ float wredmax(float v) {
#pragma unroll
    for (int o = 16; o > 0; o >>= 1) v = fmaxf(v, __shfl_xor_sync(0xffffffffu, v, o));
    return v;
}
__device__ __forceinline__ unsigned long long wredmaxu64(unsigned long long v) {
#pragma unroll
    for (int o = 16; o > 0; o >>= 1) {
        unsigned long long q = __shfl_xor_sync(0xffffffffu, v, o);
        if (q > v) v = q;
    }
    return v;
}

__device__ __forceinline__ unsigned long long packf(float v, int idx) {
    unsigned u = __float_as_uint(v);
    u = (u & 0x80000000u) ? ~u : (u | 0x80000000u);   // totally ordered float bits
    return ((unsigned long long)u << 32) | (unsigned)(~(unsigned)idx); // tie -> lowest idx
}
__device__ __forceinline__ float unpack_max(unsigned long long p) {
    unsigned u = (unsigned)(p >> 32);
    unsigned b = (u & 0x80000000u) ? (u & 0x7fffffffu) : ~u;
    return __uint_as_float(b);
}
__device__ __forceinline__ int unpack_idx(unsigned long long p) {
    return (int)(~(unsigned)(p & 0xffffffffu));
}

__device__ __forceinline__ float dot4(float4 a, float4 b) {
    return a.x * b.x + a.y * b.y + a.z * b.z + a.w * b.w;
}

// 8-elem bf16 dot against two float4 halves
__device__ __forceinline__ float bfdot8(uint4 w, float4 a, float4 b) {
    float2 p0 = __bfloat1622float2(*(__nv_bfloat162*)&w.x);
    float2 p1 = __bfloat1622float2(*(__nv_bfloat162*)&w.y);
    float2 p2 = __bfloat1622float2(*(__nv_bfloat162*)&w.z);
    float2 p3 = __bfloat1622float2(*(__nv_bfloat162*)&w.w);
    return p0.x*a.x + p0.y*a.y + p1.x*a.z + p1.y*a.w
         + p2.x*b.x + p2.y*b.y + p3.x*b.z + p3.y*b.w;
}

// insert p into descending top-4 (c0>=c1>=c2>=c3)
__device__ __forceinline__ void top4_ins(unsigned long long& c0, unsigned long long& c1,
                                         unsigned long long& c2, unsigned long long& c3,
                                         unsigned long long p) {
    if (p > c0)      { c3 = c2; c2 = c1; c1 = c0; c0 = p; }
    else if (p > c1) { c3 = c2; c2 = c1; c1 = p; }
    else if (p > c2) { c3 = c2; c2 = p; }
    else if (p > c3) { c3 = p; }
}

// ---------------- grid-wide barrier (CG grid.sync pattern) ----------------
__device__ __forceinline__ unsigned ld_acq(unsigned* p) {
    unsigned v;
    asm volatile("ld.acquire.gpu.u32 %0, [%1];" : "=r"(v) : "l"(p) : "memory");
    return v;
}
__device__ __forceinline__ void st_rel(unsigned* p, unsigned v) {
    asm volatile("st.release.gpu.u32 [%0], %1;" :: "l"(p), "r"(v) : "memory");
}

__device__ __forceinline__ void gsync() {
    __syncthreads();
    if (threadIdx.x == 0) {
        unsigned gen = ld_acq(&g_bar_gen);
        __threadfence();
        if (atomicAdd(&g_bar_count, 1) == GRID - 1) {
            g_bar_count = 0;
            st_rel(&g_bar_gen, gen + 1);
        } else {
            while (ld_acq(&g_bar_gen) == gen) { }
        }
    }
    __syncthreads();
}

// ---------------- shared-memory layout ----------------
struct Smem {
    float e[ATTP];                // attention softmax weights (zero-padded)
    float slot[WPB * MAXSLOT];    // raw logits per warp slot
    float red[WPB];               // warp-level reduction scratch
    unsigned long long wtop[WPB][4];
    unsigned long long top4[4];
    unsigned long long cand[4];
    float bf[4];                  // scalar broadcasts
    unsigned long long bu;
};

// ---------------- phases ----------------

// GRU step: warp w<7 handles row = w*GRID + cta, all 6 dots.
__device__ __forceinline__ void gru_phase(
    const float* __restrict__ Wih, const float* __restrict__ Whh,
    const float* __restrict__ bih, const float* __restrict__ bhh,
    const float* __restrict__ x, const float* __restrict__ h,
    float* __restrict__ ho, int t, int write_enc)
{
    int wib = threadIdx.x >> 5;
    int lane = threadIdx.x & 31;
    if (wib >= 7) return;
    int row = wib * GRID + (int)blockIdx.x;
    if (row >= H) return;

    const float4* x4 = (const float4*)x;
    const float4* h4 = (const float4*)h;
    const float4* Wir = (const float4*)(Wih + (size_t)row * H);
    const float4* Wiz = (const float4*)(Wih + (size_t)(row + H) * H);
    const float4* Win = (const float4*)(Wih + (size_t)(row + 2 * H) * H);
    const float4* Whr = (const float4*)(Whh + (size_t)row * H);
    const float4* Whz = (const float4*)(Whh + (size_t)(row + H) * H);
    const float4* Whn = (const float4*)(Whh + (size_t)(row + 2 * H) * H);

    float ir = 0.f, iz = 0.f, inn = 0.f, hr = 0.f, hz = 0.f, hn = 0.f;
#pragma unroll 4
    for (int k = lane; k < H4; k += 32) {
        float4 xv = x4[k], hv = h4[k];
        ir  += dot4(Wir[k], xv);
        iz  += dot4(Wiz[k], xv);
        inn += dot4(Win[k], xv);
        hr  += dot4(Whr[k], hv);
        hz  += dot4(Whz[k], hv);
        hn  += dot4(Whn[k], hv);
    }
    ir = wredsum(ir);  iz = wredsum(iz);  inn = wredsum(inn);
    hr = wredsum(hr);  hz = wredsum(hz);  hn  = wredsum(hn);

    if (lane == 0) {
        ir  += bih[row];          hr += bhh[row];
        iz  += bih[row + H];      hz += bhh[row + H];
        inn += bih[row + 2 * H];  hn += bhh[row + 2 * H];
        float r = 1.f / (1.f + expf(-(ir + hr)));
        float z = 1.f / (1.f + expf(-(iz + hz)));
        float n = tanhf(inn + r * hn);
        float hnew = (1.f - z) * n + z * h[row];
        ho[row] = hnew;
        if (write_enc) g_enc_T[(size_t)row * ATTP + t] = hnew;  // transposed store
    }
}

// one-time after encoder: M[i][t] = dot(comb_W[i, H:2H], enc_out[t])
// warp per row i, lanes over t (5 chunks of 32, padded region gives zeros).
__device__ __forceinline__ void build_M(const float* __restrict__ comb_W)
{
    int wib = threadIdx.x >> 5;
    int lane = threadIdx.x & 31;
    if (wib >= 7) return;
    int row = wib * GRID + (int)blockIdx.x;
    if (row >= H) return;

    const float4* W2 = (const float4*)(comb_W + (size_t)row * 2 * H + H);
    float a0 = 0.f, a1 = 0.f, a2 = 0.f, a3 = 0.f, a4 = 0.f;
#pragma unroll 2
    for (int j4 = 0; j4 < H4; j4++) {
        float4 w = W2[j4];
        const float* E = g_enc_T + (size_t)(j4 * 4) * ATTP + lane;
#pragma unroll
        for (int c = 0; c < 4; c++) {
            float wc = (c == 0) ? w.x : (c == 1) ? w.y : (c == 2) ? w.z : w.w;
            const float* Ec = E + (size_t)c * ATTP;
            a0 += wc * Ec[0];
            a1 += wc * Ec[32];
            a2 += wc * Ec[64];
            a3 += wc * Ec[96];
            a4 += wc * Ec[128];
        }
    }
    float* Mr = g_M + (size_t)row * ATTP;
    Mr[lane]       = a0;
    Mr[lane + 32]  = a1;
    Mr[lane + 64]  = a2;
    Mr[lane + 96]  = a3;
    Mr[lane + 128] = a4;
}

// comb = relu(W1@emb + (M @ e)/S + b), softmax folded in (warp 15),
// warps 0..6 do the row dots. ctx phase eliminated via precomputed M.
__device__ __forceinline__ void comb_phase(
    const float* __restrict__ comb_W, const float* __restrict__ comb_b,
    const float* __restrict__ dec_emb, Smem* sm)
{
    int wib = threadIdx.x >> 5;
    int lane = threadIdx.x & 31;
    int tok = g_tok;

    if (wib == 15) {   // local softmax of the 129 attention logits
        float v[5];
        float mx = -INFINITY;
#pragma unroll
        for (int k = 0; k < 5; k++) {
            int idx = lane + 32 * k;
            v[k] = (idx < ATT) ? g_attn[idx] : -INFINITY;
            mx = fmaxf(mx, v[k]);
        }
        mx = wredmax(mx);
        float s = 0.f;
#pragma unroll
        for (int k = 0; k < 5; k++) {
            int idx = lane + 32 * k;
            float e = (idx < ATT) ? expf(v[k] - mx) : 0.f;
            sm->e[idx] = e;        // idx < 160 always; pads are zero
            s += e;
        }
        s = wredsum(s);
        if (lane == 0) sm->bf[0] = 1.f / s;
    }

    int row = wib * GRID + (int)blockIdx.x;
    bool act = (wib < 7) && (row < H);
    float a = 0.f;
    if (act) {
        const float4* W  = (const float4*)(comb_W + (size_t)row * 2 * H);
        const float4* e4 = (const float4*)(dec_emb + (size_t)tok * H);
#pragma unroll 8
        for (int k = lane; k < H4; k += 32) a += dot4(W[k], e4[k]);
    }
    __syncthreads();
    if (act) {
        const float* Mr = g_M + (size_t)row * ATTP;
        float b = 0.f;
#pragma unroll
        for (int k = 0; k < 5; k++) {
            int t = lane + 32 * k;
            b += sm->e[t] * Mr[t];   // pads contribute 0
        }
        float tot = a + b * sm->bf[0];
        tot = wredsum(tot);
        if (lane == 0) g_comb[row] = fmaxf(tot + comb_b[row], 0.f);
    }
}

// one warp-GEMV row quad: policies are compile-time (NRES = # of __ldg rows of the 4)
template<int NRES>
__device__ __forceinline__ void logits_quad(
    int r0, int r1, int r2, int r3, const float4* hv,
    const float* __restrict__ out_b, float* slotp,
    int s0, int s1, int s2, int s3, int lane)
{
    const uint4* W0 = (const uint4*)(g_wbf + (size_t)r0 * H);
    const uint4* W1 = (const uint4*)(g_wbf + (size_t)r1 * H);
    const uint4* W2 = (const uint4*)(g_wbf + (size_t)r2 * H);
    const uint4* W3 = (const uint4*)(g_wbf + (size_t)r3 * H);
    float a0 = 0.f, a1 = 0.f, a2 = 0.f, a3 = 0.f;
#pragma unroll
    for (int i = 0; i < 4; i++) {
        uint4 w0 = (NRES > 0) ? __ldg(&W0[lane + 32*i]) : __ldcs(&W0[lane + 32*i]);
        uint4 w1 = (NRES > 1) ? __ldg(&W1[lane + 32*i]) : __ldcs(&W1[lane + 32*i]);
        uint4 w2 = (NRES > 2) ? __ldg(&W2[lane + 32*i]) : __ldcs(&W2[lane + 32*i]);
        uint4 w3 = (NRES > 3) ? __ldg(&W3[lane + 32*i]) : __ldcs(&W3[lane + 32*i]);
        a0 += bfdot8(w0, hv[2*i], hv[2*i+1]);
        a1 += bfdot8(w1, hv[2*i], hv[2*i+1]);
        a2 += bfdot8(w2, hv[2*i], hv[2*i+1]);
        a3 += bfdot8(w3, hv[2*i], hv[2*i+1]);
    }
    a0 = wredsum(a0);
    a1 = wredsum(a1);
    a2 = wredsum(a2);
    a3 = wredsum(a3);
    if (lane == 0) {
        a0 += out_b[r0];  g_logits[r0] = a0;  slotp[s0] = a0;
        a1 += out_b[r1];  g_logits[r1] = a1;  slotp[s1] = a1;
        a2 += out_b[r2];  g_logits[r2] = a2;  slotp[s2] = a2;
        a3 += out_b[r3];  g_logits[r3] = a3;  slotp[s3] = a3;
    }
}

// logits GEMV on bf16 weights: split residency (slots 0..7 resident, 8..13 streamed)
__device__ __forceinline__ void logits_phase(
    const float* __restrict__ out_b, const float* __restrict__ h, Smem* sm)
{
    int tid = threadIdx.x, lane = tid & 31, wib = tid >> 5;
    int gw = (int)blockIdx.x * WPB + wib;

    if (tid < WPB * MAXSLOT) sm->slot[tid] = -INFINITY;
    __syncthreads();

    const float4* h4 = (const float4*)h;
    float4 hv[8];
#pragma unroll
    for (int i = 0; i < 4; i++) {
        hv[2*i]   = h4[(lane + 32*i) * 2];
        hv[2*i+1] = h4[(lane + 32*i) * 2 + 1];
    }
    float* slotp = sm->slot + wib * MAXSLOT;

    logits_quad<2>(gw + 0*NWARPS, gw + 1*NWARPS, gw +  8*NWARPS, gw +  9*NWARPS,
                   hv, out_b, slotp, 0, 1, 8, 9, lane);
    logits_quad<2>(gw + 2*NWARPS, gw + 3*NWARPS, gw + 10*NWARPS, gw + 11*NWARPS,
                   hv, out_b, slotp, 2, 3, 10, 11, lane);
    logits_quad<3>(gw + 4*NWARPS, gw + 5*NWARPS, gw +  6*NWARPS, gw + 12*NWARPS,
                   hv, out_b, slotp, 4, 5, 6, 12, lane);
    // tail: slot 7 (resident, always valid) + slot 13 (streamed, conditional)
    {
        int r0 = gw + 7 * NWARPS;
        int r1 = gw + 13 * NWARPS;
        bool ok1 = (r1 < VOUT);
        const uint4* W0 = (const uint4*)(g_wbf + (size_t)r0 * H);
        const uint4* W1 = (const uint4*)(g_wbf + (size_t)(ok1 ? r1 : r0) * H);
        float a0 = 0.f, a1 = 0.f;
#pragma unroll
        for (int i = 0; i < 4; i++) {
            uint4 w0 = __ldg (&W0[lane + 32 * i]);
            uint4 w1 = __ldcs(&W1[lane + 32 * i]);
            a0 += bfdot8(w0, hv[2*i], hv[2*i+1]);
            a1 += bfdot8(w1, hv[2*i], hv[2*i+1]);
        }
        a0 = wredsum(a0);
        a1 = wredsum(a1);
        if (lane == 0) {
            a0 += out_b[r0];  g_logits[r0] = a0;  slotp[7] = a0;
            if (ok1) {
                a1 += out_b[r1];  g_logits[r1] = a1;  slotp[13] = a1;
            }
        }
    }

    // per-warp top-4 scan (lane0, off the hot loop)
    if (lane == 0) {
        unsigned long long c0 = 0, c1 = 0, c2 = 0, c3 = 0;
#pragma unroll
        for (int n = 0; n < MAXSLOT; n++) {
            int row = gw + n * NWARPS;
            if (row < VOUT) {
                unsigned long long p = packf(slotp[n], row);
                top4_ins(c0, c1, c2, c3, p);
            }
        }
        sm->wtop[wib][0] = c0; sm->wtop[wib][1] = c1;
        sm->wtop[wib][2] = c2; sm->wtop[wib][3] = c3;
    }
    __syncthreads();

    // warp0: pop-merge 16 warp lists -> CTA top-4
    if (wib == 0) {
        unsigned long long a0 = 0, a1 = 0, a2 = 0, a3 = 0;
        if (lane < WPB) {
            a0 = sm->wtop[lane][0]; a1 = sm->wtop[lane][1];
            a2 = sm->wtop[lane][2]; a3 = sm->wtop[lane][3];
        }
        int pos = 0;
        unsigned long long t[4];
#pragma unroll
        for (int k = 0; k < 4; k++) {
            unsigned long long head = (pos == 0) ? a0 : (pos == 1) ? a1 :
                                      (pos == 2) ? a2 : (pos == 3) ? a3 : 0ull;
            unsigned long long m = wredmaxu64(head);
            t[k] = m;
            if (head == m && pos < 4) pos++;
        }
        if (lane == 0) {
#pragma unroll
            for (int k = 0; k < 4; k++) g_ptop[blockIdx.x][k] = t[k];
            sm->bu = t[0];
        }
    }
    __syncthreads();

    // CTA sumexp wrt CTA max: warp-level (slots 0..223 covered by warps 0..6)
    {
        float m = unpack_max(sm->bu);
        float e = (tid < WPB * MAXSLOT) ? expf(sm->slot[tid] - m) : 0.f;
        e = wredsum(e);
        if (lane == 0) sm->red[wib] = e;
        __syncthreads();
        if (tid == 0) {
            float S = 0.f;
#pragma unroll
            for (int i = 0; i < 7; i++) S += sm->red[i];
            g_psum[blockIdx.x] = S;
        }
    }
}

// global top-4 merge + lse; fp32 recheck of top-4 for exact argmax;
// write logp row; fuse next-step attention-logit prep
__device__ __forceinline__ void out_phase(
    float* __restrict__ out, int step,
    const float* __restrict__ out_W, const float* __restrict__ out_b,
    const float* __restrict__ attn_W, const float* __restrict__ attn_b,
    const float* __restrict__ dec_emb, const float* __restrict__ h, Smem* sm)
{
    int tid = threadIdx.x, lane = tid & 31, wib = tid >> 5;

    if (wib == 0) {
        unsigned long long c0 = 0, c1 = 0, c2 = 0, c3 = 0;
        for (int cc = lane; cc < GRID; cc += 32) {
#pragma unroll
            for (int k = 0; k < 4; k++)
                top4_ins(c0, c1, c2, c3, g_ptop[cc][k]);
        }
        int pos = 0;
        unsigned long long t[4];
#pragma unroll
        for (int k = 0; k < 4; k++) {
            unsigned long long head = (pos == 0) ? c0 : (pos == 1) ? c1 :
                                      (pos == 2) ? c2 : (pos == 3) ? c3 : 0ull;
            unsigned long long mm = wredmaxu64(head);
            t[k] = mm;
            if (head == mm && pos < 4) pos++;
        }
        float M = unpack_max(t[0]);
        float S = 0.f;
        for (int cc = lane; cc < GRID; cc += 32)
            S += g_psum[cc] * expf(unpack_max(g_ptop[cc][0]) - M);
        S = wredsum(S);
        if (lane == 0) {
#pragma unroll
            for (int k = 0; k < 4; k++) sm->top4[k] = t[k];
            sm->bf[0] = M + logf(S);
        }
    }
    __syncthreads();
    float lse = sm->bf[0];

    int g = (int)blockIdx.x * BLOCK + tid;
    if (g < VOUT) out[(size_t)step * VOUT + g] = g_logits[g] - lse;

    // fp32 recheck of the 4 candidates (warps 0..3, one row each)
    if (wib < 4) {
        int rk = unpack_idx(sm->top4[wib]);
        const float4* W = (const float4*)(out_W + (size_t)rk * H);
        const float4* h4 = (const float4*)h;
        float a = 0.f;
#pragma unroll 4
        for (int k = lane; k < H4; k += 32) a += dot4(W[k], h4[k]);
        a = wredsum(a);
        if (lane == 0) sm->cand[wib] = packf(a + out_b[rk], rk);
    }
    __syncthreads();
    unsigned long long w = sm->cand[0];
#pragma unroll
    for (int k = 1; k < 4; k++) if (sm->cand[k] > w) w = sm->cand[k];
    int tok = unpack_idx(w);

    // next-step attention logits: two-warp split per CTA row
    if ((int)blockIdx.x < ATT) {
        int r = (int)blockIdx.x;
        if (wib == 0) {        // emb half
            const float4* W  = (const float4*)(attn_W + (size_t)r * 2 * H);
            const float4* e4 = (const float4*)(dec_emb + (size_t)tok * H);
            float a = 0.f;
#pragma unroll 4
            for (int k = lane; k < H4; k += 32) a += dot4(W[k], e4[k]);
            a = wredsum(a);
            if (lane == 0) sm->bf[1] = a;
        } else if (wib == 8) { // h half
            const float4* W  = (const float4*)(attn_W + (size_t)r * 2 * H + H);
            const float4* h4 = (const float4*)h;
            float a = 0.f;
#pragma unroll 4
            for (int k = lane; k < H4; k += 32) a += dot4(W[k], h4[k]);
            a = wredsum(a);
            if (lane == 0) sm->bf[2] = a;
        }
        __syncthreads();
        if (tid == 0) g_attn[r] = sm->bf[1] + sm->bf[2] + attn_b[r];
    }
    if (blockIdx.x == 0 && tid == 0) g_tok = tok;
}

// ---------------- the single persistent kernel ----------------
__global__ void __launch_bounds__(BLOCK, 1) k_all(
    const int* __restrict__ tokens,
    const float* __restrict__ enc_emb,
    const float* __restrict__ enc_Wih, const float* __restrict__ enc_Whh,
    const float* __restrict__ enc_bih, const float* __restrict__ enc_bhh,
    const float* __restrict__ dec_emb,
    const float* __restrict__ attn_W, const float* __restrict__ attn_b,
    const float* __restrict__ comb_W, const float* __restrict__ comb_b,
    const float* __restrict__ dec_Wih, const float* __restrict__ dec_Whh,
    const float* __restrict__ dec_bih, const float* __restrict__ dec_bhh,
    const float* __restrict__ out_W, const float* __restrict__ out_b,
    float* __restrict__ out)
{
    __shared__ Smem sm;
    int tid = threadIdx.x;

    // one-time: convert out_W to bf16 (grid-stride, vectorized)
    {
        const float4* w4 = (const float4*)out_W;
        uint2* dst = (uint2*)g_wbf;
        const int n4 = VOUT * (H / 4);
        for (int i = (int)blockIdx.x * BLOCK + tid; i < n4; i += GRID * BLOCK) {
            float4 v = __ldcs(&w4[i]);
            __nv_bfloat162 lo = __floats2bfloat162_rn(v.x, v.y);
            __nv_bfloat162 hi = __floats2bfloat162_rn(v.z, v.w);
            uint2 o;
            o.x = *(unsigned*)&lo;
            o.y = *(unsigned*)&hi;
            dst[i] = o;
        }
    }

    // init: h0 = 0, zero enc_T (padding columns must be 0)
    {
        int gt = (int)blockIdx.x * BLOCK + tid;
        if (gt < H) g_h[0][gt] = 0.f;
        for (int i = gt; i < H * ATTP; i += GRID * BLOCK) g_enc_T[i] = 0.f;
    }
    gsync();

    // ---- encoder (writes transposed enc_T) ----
    for (int t = 0; t < ML; t++) {
        const float* x = enc_emb + (size_t)tokens[t] * H;
        gru_phase(enc_Wih, enc_Whh, enc_bih, enc_bhh, x,
                  g_h[t & 1], g_h[(t & 1) ^ 1], t, 1);
        gsync();
    }
    // final encoder hidden in g_h[0]

    // ---- build M (warps 0..6) + decoder prep (warps 8,9) in one phase ----
    build_M(comb_W);
    if ((int)blockIdx.x < ATT) {
        int r = (int)blockIdx.x;
        int wib = tid >> 5, lane = tid & 31;
        if (wib == 8) {        // emb half (tok = SOS = 0)
            const float4* W  = (const float4*)(attn_W + (size_t)r * 2 * H);
            const float4* e4 = (const float4*)dec_emb;
            float a = 0.f;
#pragma unroll 4
            for (int k = lane; k < H4; k += 32) a += dot4(W[k], e4[k]);
            a = wredsum(a);
            if (lane == 0) sm.bf[1] = a;
        } else if (wib == 9) { // h half
            const float4* W  = (const float4*)(attn_W + (size_t)r * 2 * H + H);
            const float4* h4 = (const float4*)g_h[0];
            float a = 0.f;
#pragma unroll 4
            for (int k = lane; k < H4; k += 32) a += dot4(W[k], h4[k]);
            a = wredsum(a);
            if (lane == 0) sm.bf[2] = a;
        }
    }
    __syncthreads();
    if ((int)blockIdx.x < ATT && tid == 0)
        g_attn[blockIdx.x] = sm.bf[1] + sm.bf[2] + attn_b[blockIdx.x];
    if (blockIdx.x == 0 && tid == 0) g_tok = 0;
    gsync();

    // ---- decoder: 4 barriers per step ----
    for (int s = 0; s < ML; s++) {
        const float* hc = g_h[s & 1];
        float* hn = g_h[(s & 1) ^ 1];

        comb_phase(comb_W, comb_b, dec_emb, &sm);              gsync();
        gru_phase(dec_Wih, dec_Whh, dec_bih, dec_bhh,
                  g_comb, hc, hn, 0, 0);                       gsync();
        logits_phase(out_b, hn, &sm);                          gsync();
        out_phase(out, s, out_W, out_b, attn_W, attn_b,
                  dec_emb, hn, &sm);                           gsync();
    }
}

// ---------------- host launcher ----------------
extern "C" void kernel_launch(void* const* d_in, const int* in_sizes, int n_in,
                              void* d_out, int out_size)
{
    const int*   tokens  = (const int*)  d_in[0];
    // d_in[1] = max_length (compile-time ML=128)
    const float* enc_emb = (const float*)d_in[2];
    const float* enc_Wih = (const float*)d_in[3];
    const float* enc_Whh = (const float*)d_in[4];
    const float* enc_bih = (const float*)d_in[5];
    const float* enc_bhh = (const float*)d_in[6];
    const float* dec_emb = (const float*)d_in[7];
    const float* attn_W  = (const float*)d_in[8];
    const float* attn_b  = (const float*)d_in[9];
    const float* comb_W  = (const float*)d_in[10];
    const float* comb_b  = (const float*)d_in[11];
    const float* dec_Wih = (const float*)d_in[12];
    const float* dec_Whh = (const float*)d_in[13];
    const float* dec_bih = (const float*)d_in[14];
    const float* dec_bhh = (const float*)d_in[15];
    const float* out_W   = (const float*)d_in[16];
    const float* out_b   = (const float*)d_in[17];
    float* out = (float*)d_out;

    k_all<<<GRID, BLOCK>>>(tokens, enc_emb, enc_Wih, enc_Whh, enc_bih, enc_bhh,
                           dec_emb, attn_W, attn_b, comb_W, comb_b,
                           dec_Wih, dec_Whh, dec_bih, dec_bhh,
                           out_W, out_b, out);
}

// round 11
// speedup vs baseline: 1.3070x; 1.0305x over previous
#include <cuda_runtime.h>
#include <cuda_bf16.h>
#include <math.h>

#define H      1024
#define H4     256          // H/4
#define VOUT   32000
#define ML     128
#define ATT    129          // ML + 1
#define ATTP   160          // padded attention length (multiple of 32)
#define GRID   148
#define BLOCK  512
#define WPB    (BLOCK/32)   // 16 warps per block
#define NWARPS (GRID*WPB)   // 2368
#define MAXSLOT 14          // max rows per warp
// logits slots 0..7 (38.9MB) stay L2-resident via __ldg;
// slots 8..13 (26.7MB) stream from DRAM via __ldcs.

// ---------------- device scratch (static, no allocation) ----------------
__device__ float g_h[2][H];
__device__ float g_enc_T[(size_t)H * ATTP];    // transposed encoder outputs [j][t]
__device__ float g_M[(size_t)H * ATTP];        // M[i][t] = dot(W2[i], enc_out[t])
__device__ float g_attn[ATT];
__device__ float g_comb[H];
__device__ float g_logits[VOUT];
__device__ unsigned long long g_ptop[GRID][4]; // per-CTA top-4 packed (bf16-based)
__device__ float g_psum[GRID];                 // per-CTA sumexp wrt its own max
__device__ int g_tok;
__device__ __nv_bfloat16 g_wbf[(size_t)VOUT * H];  // 64MB bf16 copy of out_W

__device__ unsigned g_bar_count = 0;
__device__ unsigned g_bar_gen   = 0;

// ---------------- helpers ----------------
__device__ __forceinline__ float wredsum(float v) {
#pragma unroll
    for (int o = 16; o > 0; o >>= 1) v += __shfl_xor_sync(0xffffffffu, v, o);
    return v;
}
__device__ __forceinline__ float wredmax(float v) {
#pragma unroll
    for (int o = 16; o > 0; o >>= 1) v = fmaxf(v, __shfl_xor_sync(0xffffffffu, v, o));
    return v;
}
__device__ __forceinline__ unsigned long long wredmaxu64(unsigned long long v) {
#pragma unroll
    for (int o = 16; o > 0; o >>= 1) {
        unsigned long long q = __shfl_xor_sync(0xffffffffu, v, o);
        if (q > v) v = q;
    }
    return v;
}

__device__ __forceinline__ unsigned long long packf(float v, int idx) {
    unsigned u = __float_as_uint(v);
    u = (u & 0x80000000u) ? ~u : (u | 0x80000000u);   // totally ordered float bits
    return ((unsigned long long)u << 32) | (unsigned)(~(unsigned)idx); // tie -> lowest idx
}
__device__ __forceinline__ float unpack_max(unsigned long long p) {
    unsigned u = (unsigned)(p >> 32);
    unsigned b = (u & 0x80000000u) ? (u & 0x7fffffffu) : ~u;
    return __uint_as_float(b);
}
__device__ __forceinline__ int unpack_idx(unsigned long long p) {
    return (int)(~(unsigned)(p & 0xffffffffu));
}

__device__ __forceinline__ float dot4(float4 a, float4 b) {
    return a.x * b.x + a.y * b.y + a.z * b.z + a.w * b.w;
}

// 8-elem bf16 dot against two float4 halves
__device__ __forceinline__ float bfdot8(uint4 w, float4 a, float4 b) {
    float2 p0 = __bfloat1622float2(*(__nv_bfloat162*)&w.x);
    float2 p1 = __bfloat1622float2(*(__nv_bfloat162*)&w.y);
    float2 p2 = __bfloat1622float2(*(__nv_bfloat162*)&w.z);
    float2 p3 = __bfloat1622float2(*(__nv_bfloat162*)&w.w);
    return p0.x*a.x + p0.y*a.y + p1.x*a.z + p1.y*a.w
         + p2.x*b.x + p2.y*b.y + p3.x*b.z + p3.y*b.w;
}

// insert p into descending top-4 (c0>=c1>=c2>=c3)
__device__ __forceinline__ void top4_ins(unsigned long long& c0, unsigned long long& c1,
                                         unsigned long long& c2, unsigned long long& c3,
                                         unsigned long long p) {
    if (p > c0)      { c3 = c2; c2 = c1; c1 = c0; c0 = p; }
    else if (p > c1) { c3 = c2; c2 = c1; c1 = p; }
    else if (p > c2) { c3 = c2; c2 = p; }
    else if (p > c3) { c3 = p; }
}

// ---------------- grid-wide barrier (CG grid.sync pattern) ----------------
__device__ __forceinline__ unsigned ld_acq(unsigned* p) {
    unsigned v;
    asm volatile("ld.acquire.gpu.u32 %0, [%1];" : "=r"(v) : "l"(p) : "memory");
    return v;
}
__device__ __forceinline__ void st_rel(unsigned* p, unsigned v) {
    asm volatile("st.release.gpu.u32 [%0], %1;" :: "l"(p), "r"(v) : "memory");
}

__device__ __forceinline__ void gsync() {
    __syncthreads();
    if (threadIdx.x == 0) {
        unsigned gen = ld_acq(&g_bar_gen);
        __threadfence();
        if (atomicAdd(&g_bar_count, 1) == GRID - 1) {
            g_bar_count = 0;
            st_rel(&g_bar_gen, gen + 1);
        } else {
            while (ld_acq(&g_bar_gen) == gen) { }
        }
    }
    __syncthreads();
}

// ---------------- shared-memory layout ----------------
struct Smem {
    float e[ATTP];                // attention softmax weights (zero-padded)
    float slot[WPB * MAXSLOT];    // raw logits per warp slot
    float red[WPB];               // warp-level reduction scratch
    float gh[8][4];               // parked Whh@h gate sums (row-warp exchange)
    unsigned long long wtop[WPB][4];
    unsigned long long top4[4];
    unsigned long long cand[4];
    float bf[4];                  // scalar broadcasts
    unsigned long long bu;
};

// ---------------- phases ----------------

// Encoder GRU step, warp-pair split: warps 0..6 x-side (Wih), warps 8..14
// h-side (Whh), combined via smem + one __syncthreads. Same math order as
// the fused version (3 dots per side, wredsum each).
__device__ __forceinline__ void gru_phase_enc(
    const float* __restrict__ Wih, const float* __restrict__ Whh,
    const float* __restrict__ bih, const float* __restrict__ bhh,
    const float* __restrict__ x, const float* __restrict__ h,
    float* __restrict__ ho, int t, Smem* sm)
{
    int wib = threadIdx.x >> 5;
    int lane = threadIdx.x & 31;
    int wp = wib & 7;
    bool xs = (wib < 7);
    bool hs = (wib >= 8 && wib < 15);
    int row = wp * GRID + (int)blockIdx.x;
    bool act = (xs || hs) && row < H;

    float a0 = 0.f, a1 = 0.f, a2 = 0.f;
    if (act) {
        const float*  W  = xs ? Wih : Whh;
        const float4* v4 = (const float4*)(xs ? x : h);
        const float4* W0 = (const float4*)(W + (size_t)row * H);
        const float4* W1 = (const float4*)(W + (size_t)(row + H) * H);
        const float4* W2 = (const float4*)(W + (size_t)(row + 2 * H) * H);
#pragma unroll 4
        for (int k = lane; k < H4; k += 32) {
            float4 vv = v4[k];
            a0 += dot4(W0[k], vv);
            a1 += dot4(W1[k], vv);
            a2 += dot4(W2[k], vv);
        }
        a0 = wredsum(a0); a1 = wredsum(a1); a2 = wredsum(a2);
        if (hs && lane == 0) {
            sm->gh[wp][0] = a0 + bhh[row];
            sm->gh[wp][1] = a1 + bhh[row + H];
            sm->gh[wp][2] = a2 + bhh[row + 2 * H];
        }
    }
    __syncthreads();
    if (act && xs && lane == 0) {
        float ir  = a0 + bih[row];
        float iz  = a1 + bih[row + H];
        float inn = a2 + bih[row + 2 * H];
        float hr = sm->gh[wp][0];
        float hz = sm->gh[wp][1];
        float hn = sm->gh[wp][2];
        float r = 1.f / (1.f + expf(-(ir + hr)));
        float z = 1.f / (1.f + expf(-(iz + hz)));
        float n = tanhf(inn + r * hn);
        float hnew = (1.f - z) * n + z * h[row];
        ho[row] = hnew;
        g_enc_T[(size_t)row * ATTP + t] = hnew;  // transposed store
    }
}

// one-time after encoder: M[i][t] = dot(comb_W[i, H:2H], enc_out[t])
__device__ __forceinline__ void build_M(const float* __restrict__ comb_W)
{
    int wib = threadIdx.x >> 5;
    int lane = threadIdx.x & 31;
    if (wib >= 7) return;
    int row = wib * GRID + (int)blockIdx.x;
    if (row >= H) return;

    const float4* W2 = (const float4*)(comb_W + (size_t)row * 2 * H + H);
    float a0 = 0.f, a1 = 0.f, a2 = 0.f, a3 = 0.f, a4 = 0.f;
#pragma unroll 2
    for (int j4 = 0; j4 < H4; j4++) {
        float4 w = W2[j4];
        const float* E = g_enc_T + (size_t)(j4 * 4) * ATTP + lane;
#pragma unroll
        for (int c = 0; c < 4; c++) {
            float wc = (c == 0) ? w.x : (c == 1) ? w.y : (c == 2) ? w.z : w.w;
            const float* Ec = E + (size_t)c * ATTP;
            a0 += wc * Ec[0];
            a1 += wc * Ec[32];
            a2 += wc * Ec[64];
            a3 += wc * Ec[96];
            a4 += wc * Ec[128];
        }
    }
    float* Mr = g_M + (size_t)row * ATTP;
    Mr[lane]       = a0;
    Mr[lane + 32]  = a1;
    Mr[lane + 64]  = a2;
    Mr[lane + 96]  = a3;
    Mr[lane + 128] = a4;
}

// decoder phase A: comb rows (w0-6) + softmax (w15) + Whh@hc dots (w8-14,
// parked in smem for the next phase). ctx eliminated via precomputed M.
__device__ __forceinline__ void comb_whh_phase(
    const float* __restrict__ comb_W, const float* __restrict__ comb_b,
    const float* __restrict__ dec_emb,
    const float* __restrict__ dec_Whh, const float* __restrict__ dec_bhh,
    const float* __restrict__ hc, Smem* sm)
{
    int wib = threadIdx.x >> 5;
    int lane = threadIdx.x & 31;
    int tok = g_tok;

    if (wib == 15) {   // local softmax of the 129 attention logits
        float v[5];
        float mx = -INFINITY;
#pragma unroll
        for (int k = 0; k < 5; k++) {
            int idx = lane + 32 * k;
            v[k] = (idx < ATT) ? g_attn[idx] : -INFINITY;
            mx = fmaxf(mx, v[k]);
        }
        mx = wredmax(mx);
        float s = 0.f;
#pragma unroll
        for (int k = 0; k < 5; k++) {
            int idx = lane + 32 * k;
            float e = (idx < ATT) ? expf(v[k] - mx) : 0.f;
            sm->e[idx] = e;        // idx < 160 always; pads are zero
            s += e;
        }
        s = wredsum(s);
        if (lane == 0) sm->bf[0] = 1.f / s;
    }

    // warps 8..14: Whh@hc gate sums for row (wib-8)*GRID + cta, parked in smem
    if (wib >= 8 && wib < 15) {
        int wp = wib - 8;
        int row = wp * GRID + (int)blockIdx.x;
        if (row < H) {
            const float4* h4 = (const float4*)hc;
            const float4* W0 = (const float4*)(dec_Whh + (size_t)row * H);
            const float4* W1 = (const float4*)(dec_Whh + (size_t)(row + H) * H);
            const float4* W2 = (const float4*)(dec_Whh + (size_t)(row + 2 * H) * H);
            float hr = 0.f, hz = 0.f, hn = 0.f;
#pragma unroll 4
            for (int k = lane; k < H4; k += 32) {
                float4 hv = h4[k];
                hr += dot4(W0[k], hv);
                hz += dot4(W1[k], hv);
                hn += dot4(W2[k], hv);
            }
            hr = wredsum(hr); hz = wredsum(hz); hn = wredsum(hn);
            if (lane == 0) {
                sm->gh[wp][0] = hr + dec_bhh[row];
                sm->gh[wp][1] = hz + dec_bhh[row + H];
                sm->gh[wp][2] = hn + dec_bhh[row + 2 * H];
            }
        }
    }

    int row = wib * GRID + (int)blockIdx.x;
    bool act = (wib < 7) && (row < H);
    float a = 0.f;
    if (act) {
        const float4* W  = (const float4*)(comb_W + (size_t)row * 2 * H);
        const float4* e4 = (const float4*)(dec_emb + (size_t)tok * H);
#pragma unroll 8
        for (int k = lane; k < H4; k += 32) a += dot4(W[k], e4[k]);
    }
    __syncthreads();
    if (act) {
        const float* Mr = g_M + (size_t)row * ATTP;
        float b = 0.f;
#pragma unroll
        for (int k = 0; k < 5; k++) {
            int t = lane + 32 * k;
            b += sm->e[t] * Mr[t];   // pads contribute 0
        }
        float tot = a + b * sm->bf[0];
        tot = wredsum(tot);
        if (lane == 0) g_comb[row] = fmaxf(tot + comb_b[row], 0.f);
    }
}

// decoder phase B: finish GRU — Wih@comb dots + gate math using parked Whh sums.
__device__ __forceinline__ void gru_fin_phase(
    const float* __restrict__ dec_Wih, const float* __restrict__ dec_bih,
    const float* __restrict__ hc, float* __restrict__ hn_out, Smem* sm)
{
    int wib = threadIdx.x >> 5;
    int lane = threadIdx.x & 31;
    if (wib >= 7) return;
    int row = wib * GRID + (int)blockIdx.x;
    if (row >= H) return;

    const float4* x4 = (const float4*)g_comb;
    const float4* W0 = (const float4*)(dec_Wih + (size_t)row * H);
    const float4* W1 = (const float4*)(dec_Wih + (size_t)(row + H) * H);
    const float4* W2 = (const float4*)(dec_Wih + (size_t)(row + 2 * H) * H);
    float ir = 0.f, iz = 0.f, inn = 0.f;
#pragma unroll 4
    for (int k = lane; k < H4; k += 32) {
        float4 xv = x4[k];
        ir  += dot4(W0[k], xv);
        iz  += dot4(W1[k], xv);
        inn += dot4(W2[k], xv);
    }
    ir = wredsum(ir); iz = wredsum(iz); inn = wredsum(inn);
    if (lane == 0) {
        ir  += dec_bih[row];
        iz  += dec_bih[row + H];
        inn += dec_bih[row + 2 * H];
        float hr = sm->gh[wib][0];
        float hz = sm->gh[wib][1];
        float hn = sm->gh[wib][2];
        float r = 1.f / (1.f + expf(-(ir + hr)));
        float z = 1.f / (1.f + expf(-(iz + hz)));
        float n = tanhf(inn + r * hn);
        hn_out[row] = (1.f - z) * n + z * hc[row];
    }
}

// one warp-GEMV row quad: policies are compile-time (NRES = # of __ldg rows of the 4)
template<int NRES>
__device__ __forceinline__ void logits_quad(
    int r0, int r1, int r2, int r3, const float4* hv,
    const float* __restrict__ out_b, float* slotp,
    int s0, int s1, int s2, int s3, int lane)
{
    const uint4* W0 = (const uint4*)(g_wbf + (size_t)r0 * H);
    const uint4* W1 = (const uint4*)(g_wbf + (size_t)r1 * H);
    const uint4* W2 = (const uint4*)(g_wbf + (size_t)r2 * H);
    const uint4* W3 = (const uint4*)(g_wbf + (size_t)r3 * H);
    float a0 = 0.f, a1 = 0.f, a2 = 0.f, a3 = 0.f;
#pragma unroll
    for (int i = 0; i < 4; i++) {
        uint4 w0 = (NRES > 0) ? __ldg(&W0[lane + 32*i]) : __ldcs(&W0[lane + 32*i]);
        uint4 w1 = (NRES > 1) ? __ldg(&W1[lane + 32*i]) : __ldcs(&W1[lane + 32*i]);
        uint4 w2 = (NRES > 2) ? __ldg(&W2[lane + 32*i]) : __ldcs(&W2[lane + 32*i]);
        uint4 w3 = (NRES > 3) ? __ldg(&W3[lane + 32*i]) : __ldcs(&W3[lane + 32*i]);
        a0 += bfdot8(w0, hv[2*i], hv[2*i+1]);
        a1 += bfdot8(w1, hv[2*i], hv[2*i+1]);
        a2 += bfdot8(w2, hv[2*i], hv[2*i+1]);
        a3 += bfdot8(w3, hv[2*i], hv[2*i+1]);
    }
    a0 = wredsum(a0);
    a1 = wredsum(a1);
    a2 = wredsum(a2);
    a3 = wredsum(a3);
    if (lane == 0) {
        a0 += out_b[r0];  g_logits[r0] = a0;  slotp[s0] = a0;
        a1 += out_b[r1];  g_logits[r1] = a1;  slotp[s1] = a1;
        a2 += out_b[r2];  g_logits[r2] = a2;  slotp[s2] = a2;
        a3 += out_b[r3];  g_logits[r3] = a3;  slotp[s3] = a3;
    }
}

// logits GEMV on bf16 weights: split residency (slots 0..7 resident, 8..13 streamed)
__device__ __forceinline__ void logits_phase(
    const float* __restrict__ out_b, const float* __restrict__ h, Smem* sm)
{
    int tid = threadIdx.x, lane = tid & 31, wib = tid >> 5;
    int gw = (int)blockIdx.x * WPB + wib;

    if (tid < WPB * MAXSLOT) sm->slot[tid] = -INFINITY;
    __syncthreads();

    const float4* h4 = (const float4*)h;
    float4 hv[8];
#pragma unroll
    for (int i = 0; i < 4; i++) {
        hv[2*i]   = h4[(lane + 32*i) * 2];
        hv[2*i+1] = h4[(lane + 32*i) * 2 + 1];
    }
    float* slotp = sm->slot + wib * MAXSLOT;

    logits_quad<2>(gw + 0*NWARPS, gw + 1*NWARPS, gw +  8*NWARPS, gw +  9*NWARPS,
                   hv, out_b, slotp, 0, 1, 8, 9, lane);
    logits_quad<2>(gw + 2*NWARPS, gw + 3*NWARPS, gw + 10*NWARPS, gw + 11*NWARPS,
                   hv, out_b, slotp, 2, 3, 10, 11, lane);
    logits_quad<3>(gw + 4*NWARPS, gw + 5*NWARPS, gw +  6*NWARPS, gw + 12*NWARPS,
                   hv, out_b, slotp, 4, 5, 6, 12, lane);
    // tail: slot 7 (resident, always valid) + slot 13 (streamed, conditional)
    {
        int r0 = gw + 7 * NWARPS;
        int r1 = gw + 13 * NWARPS;
        bool ok1 = (r1 < VOUT);
        const uint4* W0 = (const uint4*)(g_wbf + (size_t)r0 * H);
        const uint4* W1 = (const uint4*)(g_wbf + (size_t)(ok1 ? r1 : r0) * H);
        float a0 = 0.f, a1 = 0.f;
#pragma unroll
        for (int i = 0; i < 4; i++) {
            uint4 w0 = __ldg (&W0[lane + 32 * i]);
            uint4 w1 = __ldcs(&W1[lane + 32 * i]);
            a0 += bfdot8(w0, hv[2*i], hv[2*i+1]);
            a1 += bfdot8(w1, hv[2*i], hv[2*i+1]);
        }
        a0 = wredsum(a0);
        a1 = wredsum(a1);
        if (lane == 0) {
            a0 += out_b[r0];  g_logits[r0] = a0;  slotp[7] = a0;
            if (ok1) {
                a1 += out_b[r1];  g_logits[r1] = a1;  slotp[13] = a1;
            }
        }
    }

    // per-warp top-4 scan (lane0, off the hot loop)
    if (lane == 0) {
        unsigned long long c0 = 0, c1 = 0, c2 = 0, c3 = 0;
#pragma unroll
        for (int n = 0; n < MAXSLOT; n++) {
            int row = gw + n * NWARPS;
            if (row < VOUT) {
                unsigned long long p = packf(slotp[n], row);
                top4_ins(c0, c1, c2, c3, p);
            }
        }
        sm->wtop[wib][0] = c0; sm->wtop[wib][1] = c1;
        sm->wtop[wib][2] = c2; sm->wtop[wib][3] = c3;
    }
    __syncthreads();

    // warp0: pop-merge 16 warp lists -> CTA top-4
    if (wib == 0) {
        unsigned long long a0 = 0, a1 = 0, a2 = 0, a3 = 0;
        if (lane < WPB) {
            a0 = sm->wtop[lane][0]; a1 = sm->wtop[lane][1];
            a2 = sm->wtop[lane][2]; a3 = sm->wtop[lane][3];
        }
        int pos = 0;
        unsigned long long t[4];
#pragma unroll
        for (int k = 0; k < 4; k++) {
            unsigned long long head = (pos == 0) ? a0 : (pos == 1) ? a1 :
                                      (pos == 2) ? a2 : (pos == 3) ? a3 : 0ull;
            unsigned long long m = wredmaxu64(head);
            t[k] = m;
            if (head == m && pos < 4) pos++;
        }
        if (lane == 0) {
#pragma unroll
            for (int k = 0; k < 4; k++) g_ptop[blockIdx.x][k] = t[k];
            sm->bu = t[0];
        }
    }
    __syncthreads();

    // CTA sumexp wrt CTA max: warp-level (slots 0..223 covered by warps 0..6)
    {
        float m = unpack_max(sm->bu);
        float e = (tid < WPB * MAXSLOT) ? expf(sm->slot[tid] - m) : 0.f;
        e = wredsum(e);
        if (lane == 0) sm->red[wib] = e;
        __syncthreads();
        if (tid == 0) {
            float S = 0.f;
#pragma unroll
            for (int i = 0; i < 7; i++) S += sm->red[i];
            g_psum[blockIdx.x] = S;
        }
    }
}

// global top-4 merge + lse; fp32 recheck of top-4 for exact argmax;
// write logp row; fuse next-step attention-logit prep
__device__ __forceinline__ void out_phase(
    float* __restrict__ out, int step,
    const float* __restrict__ out_W, const float* __restrict__ out_b,
    const float* __restrict__ attn_W, const float* __restrict__ attn_b,
    const float* __restrict__ dec_emb, const float* __restrict__ h, Smem* sm)
{
    int tid = threadIdx.x, lane = tid & 31, wib = tid >> 5;

    if (wib == 0) {
        unsigned long long c0 = 0, c1 = 0, c2 = 0, c3 = 0;
        for (int cc = lane; cc < GRID; cc += 32) {
#pragma unroll
            for (int k = 0; k < 4; k++)
                top4_ins(c0, c1, c2, c3, g_ptop[cc][k]);
        }
        int pos = 0;
        unsigned long long t[4];
#pragma unroll
        for (int k = 0; k < 4; k++) {
            unsigned long long head = (pos == 0) ? c0 : (pos == 1) ? c1 :
                                      (pos == 2) ? c2 : (pos == 3) ? c3 : 0ull;
            unsigned long long mm = wredmaxu64(head);
            t[k] = mm;
            if (head == mm && pos < 4) pos++;
        }
        float M = unpack_max(t[0]);
        float S = 0.f;
        for (int cc = lane; cc < GRID; cc += 32)
            S += g_psum[cc] * expf(unpack_max(g_ptop[cc][0]) - M);
        S = wredsum(S);
        if (lane == 0) {
#pragma unroll
            for (int k = 0; k < 4; k++) sm->top4[k] = t[k];
            sm->bf[0] = M + logf(S);
        }
    }
    __syncthreads();
    float lse = sm->bf[0];

    int g = (int)blockIdx.x * BLOCK + tid;
    if (g < VOUT) out[(size_t)step * VOUT + g] = g_logits[g] - lse;

    // fp32 recheck of the 4 candidates (warps 0..3, one row each)
    if (wib < 4) {
        int rk = unpack_idx(sm->top4[wib]);
        const float4* W = (const float4*)(out_W + (size_t)rk * H);
        const float4* h4 = (const float4*)h;
        float a = 0.f;
#pragma unroll 4
        for (int k = lane; k < H4; k += 32) a += dot4(W[k], h4[k]);
        a = wredsum(a);
        if (lane == 0) sm->cand[wib] = packf(a + out_b[rk], rk);
    }
    __syncthreads();
    unsigned long long w = sm->cand[0];
#pragma unroll
    for (int k = 1; k < 4; k++) if (sm->cand[k] > w) w = sm->cand[k];
    int tok = unpack_idx(w);

    // next-step attention logits: two-warp split per CTA row
    if ((int)blockIdx.x < ATT) {
        int r = (int)blockIdx.x;
        if (wib == 8) {        // emb half
            const float4* W  = (const float4*)(attn_W + (size_t)r * 2 * H);
            const float4* e4 = (const float4*)(dec_emb + (size_t)tok * H);
            float a = 0.f;
#pragma unroll 4
            for (int k = lane; k < H4; k += 32) a += dot4(W[k], e4[k]);
            a = wredsum(a);
            if (lane == 0) sm->bf[1] = a;
        } else if (wib == 9) { // h half
            const float4* W  = (const float4*)(attn_W + (size_t)r * 2 * H + H);
            const float4* h4 = (const float4*)h;
            float a = 0.f;
#pragma unroll 4
            for (int k = lane; k < H4; k += 32) a += dot4(W[k], h4[k]);
            a = wredsum(a);
            if (lane == 0) sm->bf[2] = a;
        }
        __syncthreads();
        if (tid == 0) g_attn[r] = sm->bf[1] + sm->bf[2] + attn_b[r];
    }
    if (blockIdx.x == 0 && tid == 0) g_tok = tok;
}

// ---------------- the single persistent kernel ----------------
__global__ void __launch_bounds__(BLOCK, 1) k_all(
    const int* __restrict__ tokens,
    const float* __restrict__ enc_emb,
    const float* __restrict__ enc_Wih, const float* __restrict__ enc_Whh,
    const float* __restrict__ enc_bih, const float* __restrict__ enc_bhh,
    const float* __restrict__ dec_emb,
    const float* __restrict__ attn_W, const float* __restrict__ attn_b,
    const float* __restrict__ comb_W, const float* __restrict__ comb_b,
    const float* __restrict__ dec_Wih, const float* __restrict__ dec_Whh,
    const float* __restrict__ dec_bih, const float* __restrict__ dec_bhh,
    const float* __restrict__ out_W, const float* __restrict__ out_b,
    float* __restrict__ out)
{
    __shared__ Smem sm;
    int tid = threadIdx.x;

    // one-time: convert out_W to bf16 (grid-stride, vectorized)
    {
        const float4* w4 = (const float4*)out_W;
        uint2* dst = (uint2*)g_wbf;
        const int n4 = VOUT * (H / 4);
        for (int i = (int)blockIdx.x * BLOCK + tid; i < n4; i += GRID * BLOCK) {
            float4 v = __ldcs(&w4[i]);
            __nv_bfloat162 lo = __floats2bfloat162_rn(v.x, v.y);
            __nv_bfloat162 hi = __floats2bfloat162_rn(v.z, v.w);
            uint2 o;
            o.x = *(unsigned*)&lo;
            o.y = *(unsigned*)&hi;
            dst[i] = o;
        }
    }

    // init: h0 = 0, zero enc_T (padding columns must be 0)
    {
        int gt = (int)blockIdx.x * BLOCK + tid;
        if (gt < H) g_h[0][gt] = 0.f;
        for (int i = gt; i < H * ATTP; i += GRID * BLOCK) g_enc_T[i] = 0.f;
    }
    gsync();

    // ---- encoder (warp-pair split, writes transposed enc_T) ----
    for (int t = 0; t < ML; t++) {
        const float* x = enc_emb + (size_t)tokens[t] * H;
        gru_phase_enc(enc_Wih, enc_Whh, enc_bih, enc_bhh, x,
                      g_h[t & 1], g_h[(t & 1) ^ 1], t, &sm);
        gsync();
    }
    // final encoder hidden in g_h[0]

    // ---- build M (warps 0..6) + decoder prep (warps 8,9) in one phase ----
    build_M(comb_W);
    if ((int)blockIdx.x < ATT) {
        int r = (int)blockIdx.x;
        int wib = tid >> 5, lane = tid & 31;
        if (wib == 8) {        // emb half (tok = SOS = 0)
            const float4* W  = (const float4*)(attn_W + (size_t)r * 2 * H);
            const float4* e4 = (const float4*)dec_emb;
            float a = 0.f;
#pragma unroll 4
            for (int k = lane; k < H4; k += 32) a += dot4(W[k], e4[k]);
            a = wredsum(a);
            if (lane == 0) sm.bf[1] = a;
        } else if (wib == 9) { // h half
            const float4* W  = (const float4*)(attn_W + (size_t)r * 2 * H + H);
            const float4* h4 = (const float4*)g_h[0];
            float a = 0.f;
#pragma unroll 4
            for (int k = lane; k < H4; k += 32) a += dot4(W[k], h4[k]);
            a = wredsum(a);
            if (lane == 0) sm.bf[2] = a;
        }
    }
    __syncthreads();
    if ((int)blockIdx.x < ATT && tid == 0)
        g_attn[blockIdx.x] = sm.bf[1] + sm.bf[2] + attn_b[blockIdx.x];
    if (blockIdx.x == 0 && tid == 0) g_tok = 0;
    gsync();

    // ---- decoder: 4 barriers per step; Whh work hidden inside comb phase ----
    for (int s = 0; s < ML; s++) {
        const float* hc = g_h[s & 1];
        float* hn = g_h[(s & 1) ^ 1];

        comb_whh_phase(comb_W, comb_b, dec_emb,
                       dec_Whh, dec_bhh, hc, &sm);             gsync();
        gru_fin_phase(dec_Wih, dec_bih, hc, hn, &sm);          gsync();
        logits_phase(out_b, hn, &sm);                          gsync();
        out_phase(out, s, out_W, out_b, attn_W, attn_b,
                  dec_emb, hn, &sm);                           gsync();
    }
}

// ---------------- host launcher ----------------
extern "C" void kernel_launch(void* const* d_in, const int* in_sizes, int n_in,
                              void* d_out, int out_size)
{
    const int*   tokens  = (const int*)  d_in[0];
    // d_in[1] = max_length (compile-time ML=128)
    const float* enc_emb = (const float*)d_in[2];
    const float* enc_Wih = (const float*)d_in[3];
    const float* enc_Whh = (const float*)d_in[4];
    const float* enc_bih = (const float*)d_in[5];
    const float* enc_bhh = (const float*)d_in[6];
    const float* dec_emb = (const float*)d_in[7];
    const float* attn_W  = (const float*)d_in[8];
    const float* attn_b  = (const float*)d_in[9];
    const float* comb_W  = (const float*)d_in[10];
    const float* comb_b  = (const float*)d_in[11];
    const float* dec_Wih = (const float*)d_in[12];
    const float* dec_Whh = (const float*)d_in[13];
    const float* dec_bih = (const float*)d_in[14];
    const float* dec_bhh = (const float*)d_in[15];
    const float* out_W   = (const float*)d_in[16];
    const float* out_b   = (const float*)d_in[17];
    float* out = (float*)d_out;

    k_all<<<GRID, BLOCK>>>(tokens, enc_emb, enc_Wih, enc_Whh, enc_bih, enc_bhh,
                           dec_emb, attn_W, attn_b, comb_W, comb_b,
                           dec_Wih, dec_Whh, dec_bih, dec_bhh,
                           out_W, out_b, out);
}